// round 10
// baseline (speedup 1.0000x reference)
#include <cuda_runtime.h>
#include <cuda_bf16.h>
#include <math.h>

#define LL 2
#define TT 512
#define BB 64
#define HH 512
#define AT 200
#define EE 512
#define VV 10000
#define SS 128
#define LTD (LL*TT)   // 1024
#define GPB 148       // persistent grid blocks (1 per SM)

// ------------------------- scratch (static device memory) -------------------------
__device__ float d_kproj[(size_t)LL*TT*BB*AT];            // fp32 GEMM out
__device__ __nv_bfloat16 d_kprojh[(size_t)LL*TT*BB*AT];   // bf16 copy (26 MB)
__device__ __nv_bfloat16 d_ench[(size_t)BB*LTD*HH];       // enc transposed (b,lt,h) bf16 (67 MB)
__device__ float d_xemb [(size_t)SS*BB*EE];
__device__ float d_giEmb[(size_t)SS*BB*3*HH];
__device__ float d_hstates[(size_t)SS*BB*HH];
__device__ float d_h0[2][BB*HH];
__device__ float d_h1[2][BB*HH];
__device__ float d_q[LL*BB*AT];
__device__ float d_scores[BB*LTD];
__device__ float d_ctxp[4*BB*HH];                         // 4 lt-split partial contexts
__device__ float d_gp[4][4][(size_t)BB*3*HH];             // GRU partials [gi0,gh0,gh1,gi1][kchunk]

// grid-barrier state (self-resetting; zero-initialized at module load)
__device__ volatile unsigned g_gen;
__device__ unsigned g_cnt;

__device__ __forceinline__ float sigm(float x){ return 1.0f/(1.0f + __expf(-x)); }
__device__ __forceinline__ float tanh_fast(float x){
    float y; asm("tanh.approx.f32 %0, %1;" : "=f"(y) : "f"(x)); return y;
}

// ------------------------- software grid barrier (GPB blocks, 1/SM) ---------------
__device__ __forceinline__ void gsync(){
    __syncthreads();
    if (threadIdx.x == 0){
        __threadfence();
        unsigned gen = g_gen;
        if (atomicAdd(&g_cnt, 1u) == (unsigned)(GPB - 1)){
            g_cnt = 0;
            __threadfence();
            g_gen = gen + 1u;
        } else {
            while (g_gen == gen) __nanosleep(64);
        }
        __threadfence();
    }
    __syncthreads();
}

// ------------------------- init h from encoder_final_states -------------------------
__global__ void k_init(const float* __restrict__ efs){
    int i = blockIdx.x*blockDim.x + threadIdx.x;
    if (i < BB*HH){ d_h0[0][i] = efs[i]; d_h1[0][i] = efs[BB*HH + i]; }
}

// ------------------------- embedding + relu for all steps -------------------------
__global__ void k_embed(const int* __restrict__ tgt, const float* __restrict__ emb){
    int sb = blockIdx.x;           // s*BB + b
    int s = sb / BB, b = sb % BB;
    int tok = (s == 0) ? 0 : tgt[b*SS + (s-1)];
    const float4* src = reinterpret_cast<const float4*>(emb + (size_t)tok*EE);
    float4* dst = reinterpret_cast<float4*>(d_xemb + (size_t)sb*EE);
    float4 v = src[threadIdx.x];
    v.x = fmaxf(v.x, 0.f); v.y = fmaxf(v.y, 0.f); v.z = fmaxf(v.z, 0.f); v.w = fmaxf(v.w, 0.f);
    dst[threadIdx.x] = v;
}

// ------------------------- bf16 converts (once) -------------------------
__global__ void k_kproj2bf(){
    size_t n2 = (size_t)LL*TT*BB*AT/2;
    for (size_t i = blockIdx.x*(size_t)blockDim.x + threadIdx.x; i < n2; i += (size_t)gridDim.x*blockDim.x){
        float2 v = reinterpret_cast<const float2*>(d_kproj)[i];
        reinterpret_cast<__nv_bfloat162*>(d_kprojh)[i] = __floats2bfloat162_rn(v.x, v.y);
    }
}
__global__ void k_enc2bf(const float* __restrict__ enc){
    int lt = blockIdx.x;   // 1024
    int tid = threadIdx.x; // 256
    for (int b = 0; b < BB; b++){
        float2 v = *reinterpret_cast<const float2*>(enc + ((size_t)lt*BB + b)*HH + 2*tid);
        reinterpret_cast<__nv_bfloat162*>(d_ench + ((size_t)b*LTD + lt)*HH)[tid] =
            __floats2bfloat162_rn(v.x, v.y);
    }
}

// ------------------------- generic fp32 NT-GEMM: C[m,n] = sum_k A[m,k]*B[n,k] -------------------------
template<bool PERM>
__global__ void __launch_bounds__(256) k_sgemm(
    const float* __restrict__ Ag, int lda, long long strideA,
    const float* __restrict__ Bg, int ldb, long long strideB,
    const float* __restrict__ bias, int strideBias,
    float* __restrict__ Cg, int ldc, long long strideC,
    int M, int N, int K)
{
    int z = blockIdx.z;
    const float* A  = Ag + (size_t)z*strideA;
    const float* Bw = Bg + (size_t)z*strideB;
    float* C = Cg + (size_t)z*strideC;
    const float* bi = bias ? (bias + (size_t)z*strideBias) : nullptr;

    __shared__ float As[16][132];
    __shared__ float Bs[16][68];

    int m0 = blockIdx.x*128, n0 = blockIdx.y*64;
    int tid = threadIdx.x;
    int ty = tid >> 4, tx = tid & 15;

    float acc[8][4];
    #pragma unroll
    for (int i=0;i<8;i++)
        #pragma unroll
        for (int j=0;j<4;j++) acc[i][j] = 0.f;

    for (int k0 = 0; k0 < K; k0 += 16){
        #pragma unroll
        for (int r=0;r<2;r++){
            int id = tid + r*256;
            int row = id >> 2, kc = (id & 3) << 2;
            float4 v = *reinterpret_cast<const float4*>(A + (size_t)(m0+row)*lda + k0 + kc);
            As[kc+0][row]=v.x; As[kc+1][row]=v.y; As[kc+2][row]=v.z; As[kc+3][row]=v.w;
        }
        {
            int row = tid >> 2, kc = (tid & 3) << 2;
            float4 v = make_float4(0.f,0.f,0.f,0.f);
            if (n0 + row < N)
                v = *reinterpret_cast<const float4*>(Bw + (size_t)(n0+row)*ldb + k0 + kc);
            Bs[kc+0][row]=v.x; Bs[kc+1][row]=v.y; Bs[kc+2][row]=v.z; Bs[kc+3][row]=v.w;
        }
        __syncthreads();
        #pragma unroll
        for (int kk=0; kk<16; kk++){
            float4 a0 = *reinterpret_cast<const float4*>(&As[kk][ty*8]);
            float4 a1 = *reinterpret_cast<const float4*>(&As[kk][ty*8+4]);
            float4 b4 = *reinterpret_cast<const float4*>(&Bs[kk][tx*4]);
            float a[8] = {a0.x,a0.y,a0.z,a0.w,a1.x,a1.y,a1.z,a1.w};
            float bb[4] = {b4.x,b4.y,b4.z,b4.w};
            #pragma unroll
            for (int i=0;i<8;i++)
                #pragma unroll
                for (int j=0;j<4;j++)
                    acc[i][j] = fmaf(a[i], bb[j], acc[i][j]);
        }
        __syncthreads();
    }

    #pragma unroll
    for (int i=0;i<8;i++){
        int m = m0 + ty*8 + i;
        #pragma unroll
        for (int j=0;j<4;j++){
            int n = n0 + tx*4 + j;
            if (n < N){
                float v = acc[i][j] + (bi ? bi[n] : 0.f);
                if (PERM){
                    int srow = m >> 6, brow = m & 63;
                    C[((size_t)brow*SS + srow)*VV + n] = v;
                } else {
                    C[(size_t)m*ldc + n] = v;
                }
            }
        }
    }
}

// =====================================================================================
// Persistent decode loop: GPB=148 blocks x 256 threads, 1 CTA/SM, full register budget.
// =====================================================================================
__global__ void __launch_bounds__(256) k_decode_loop(
    const float* __restrict__ Qw, const float* __restrict__ Qb,
    const float* __restrict__ Vw, const float* __restrict__ Vb,
    const float* __restrict__ Wih0, const float* __restrict__ Whh0, const float* __restrict__ bhh0,
    const float* __restrict__ Wih1, const float* __restrict__ bih1,
    const float* __restrict__ Whh1, const float* __restrict__ bhh1)
{
    __shared__ float sbuf[4096];   // 16KB, aliased per phase

    const int tid = threadIdx.x;
    const int bid = blockIdx.x;
    const int lane = tid & 31;

    for (int s = 0; s < SS; s++){
        const int cur = s & 1;

        // ===== P1: q = Qw @ h + Qb  (50 blocks, Qw tile in smem) =====
        if (bid < 50){
            int l = bid >= 25;
            const float4* qg = reinterpret_cast<const float4*>(Qw + (size_t)bid*8*HH);
            float4* s4 = reinterpret_cast<float4*>(sbuf);
            #pragma unroll
            for (int i=0;i<4;i++) s4[tid + i*256] = qg[tid + i*256];
            __syncthreads();
            int b = tid & 63, ap = tid >> 6;     // 2 rows per thread
            const float4* hb = reinterpret_cast<const float4*>((l ? d_h1[cur] : d_h0[cur]) + (size_t)b*HH);
            const float4* w0 = reinterpret_cast<const float4*>(sbuf + (size_t)(ap*2+0)*HH);
            const float4* w1 = reinterpret_cast<const float4*>(sbuf + (size_t)(ap*2+1)*HH);
            float a0 = 0.f, a1 = 0.f;
            #pragma unroll 8
            for (int k=0;k<128;k++){
                float4 h4 = hb[k];
                float4 x0 = w0[k], x1 = w1[k];
                a0 = fmaf(h4.x,x0.x,fmaf(h4.y,x0.y,fmaf(h4.z,x0.z,fmaf(h4.w,x0.w,a0))));
                a1 = fmaf(h4.x,x1.x,fmaf(h4.y,x1.y,fmaf(h4.z,x1.z,fmaf(h4.w,x1.w,a1))));
            }
            int gr = bid*8 + ap*2;
            int a = gr - l*200;
            d_q[(size_t)(l*BB + b)*AT + a]     = a0 + Qb[gr];
            d_q[(size_t)(l*BB + b)*AT + a + 1] = a1 + Qb[gr+1];
        }
        gsync();

        // ===== P2: scores (bf16 kproj, 4-deep row pipeline, warp per (l,b,chunk)) =====
        {
            int w = bid*8 + (tid>>5);           // 0..1183
            if (w < 1152){
                int l  = w >= 576;
                int r0 = w - l*576;
                int b  = r0 & 63;
                int ch = r0 >> 6;                // 0..8
                int lt0 = l*512 + ch*57;
                int cnt = min(57, 512 - ch*57);

                float q8[8], v8[8];
                if (lane < 25){
                    const float4* qp = reinterpret_cast<const float4*>(d_q + (size_t)(l*BB + b)*AT + lane*8);
                    const float4* vp = reinterpret_cast<const float4*>(Vw + l*AT + lane*8);
                    float4 aa = qp[0], cc = qp[1], ee = vp[0], ff = vp[1];
                    q8[0]=aa.x;q8[1]=aa.y;q8[2]=aa.z;q8[3]=aa.w;q8[4]=cc.x;q8[5]=cc.y;q8[6]=cc.z;q8[7]=cc.w;
                    v8[0]=ee.x;v8[1]=ee.y;v8[2]=ee.z;v8[3]=ee.w;v8[4]=ff.x;v8[5]=ff.y;v8[6]=ff.z;v8[7]=ff.w;
                } else {
                    #pragma unroll
                    for (int i=0;i<8;i++){ q8[i]=0.f; v8[i]=0.f; }
                }
                float vb = Vb[l];
                const uint4* kp = reinterpret_cast<const uint4*>(d_kprojh);
                size_t base = ((size_t)lt0*BB + b)*25 + lane;   // row stride = BB*25 uint4

                uint4 b0=make_uint4(0,0,0,0), b1=b0, b2=b0, b3=b0;
                if (lane < 25){
                    b0 = kp[base];
                    if (1 < cnt) b1 = kp[base + (size_t)1*BB*25];
                    if (2 < cnt) b2 = kp[base + (size_t)2*BB*25];
                    if (3 < cnt) b3 = kp[base + (size_t)3*BB*25];
                }
                #pragma unroll 1
                for (int r = 0; r < cnt; r += 4){
                    #pragma unroll
                    for (int j = 0; j < 4; j++){
                        if (r + j < cnt){
                            uint4 c4 = (j==0)?b0:(j==1)?b1:(j==2)?b2:b3;
                            // refill this slot with row r+j+4
                            if (lane < 25 && r + j + 4 < cnt){
                                uint4 nv = kp[base + (size_t)(r+j+4)*BB*25];
                                if (j==0) b0=nv; else if (j==1) b1=nv; else if (j==2) b2=nv; else b3=nv;
                            }
                            const __nv_bfloat162* p = reinterpret_cast<const __nv_bfloat162*>(&c4);
                            float sum = 0.f;
                            #pragma unroll
                            for (int t=0;t<4;t++){
                                float2 f2 = __bfloat1622float2(p[t]);
                                sum = fmaf(v8[2*t+0], tanh_fast(f2.x + q8[2*t+0]), sum);
                                sum = fmaf(v8[2*t+1], tanh_fast(f2.y + q8[2*t+1]), sum);
                            }
                            #pragma unroll
                            for (int off=16; off; off>>=1) sum += __shfl_xor_sync(0xffffffffu, sum, off);
                            if (lane == 0) d_scores[(size_t)b*LTD + lt0 + r + j] = sum + vb;
                        }
                    }
                }
            }
        }
        gsync();

        // ===== P3: softmax + partial context (units (b,c), 256 over 148 blocks) =====
        for (int u = bid; u < 256; u += GPB){
            int b = u >> 2, c = u & 3;
            float* sw = sbuf;            // 1024
            float* red = sbuf + 1024;    // 256
            float4 s4 = *reinterpret_cast<const float4*>(d_scores + (size_t)b*LTD + tid*4);
            float mx = fmaxf(fmaxf(s4.x, s4.y), fmaxf(s4.z, s4.w));
            red[tid] = mx; __syncthreads();
            for (int st=128; st>0; st>>=1){ if (tid<st) red[tid]=fmaxf(red[tid],red[tid+st]); __syncthreads(); }
            float m = red[0]; __syncthreads();
            float e0 = __expf(s4.x-m), e1 = __expf(s4.y-m), e2 = __expf(s4.z-m), e3 = __expf(s4.w-m);
            sw[tid*4+0]=e0; sw[tid*4+1]=e1; sw[tid*4+2]=e2; sw[tid*4+3]=e3;
            red[tid] = e0+e1+e2+e3; __syncthreads();
            for (int st=128; st>0; st>>=1){ if (tid<st) red[tid]+=red[tid+st]; __syncthreads(); }
            float inv = 1.0f/red[0]; __syncthreads();
            sw[c*256 + tid] *= inv;
            __syncthreads();

            const __nv_bfloat162* ep = reinterpret_cast<const __nv_bfloat162*>(d_ench) +
                                       ((size_t)b*LTD + c*256)*(HH/2) + tid;
            const float* wc = &sw[c*256];
            float ax = 0.f, ay = 0.f;
            #pragma unroll 16
            for (int j=0;j<256;j++){
                float wj = wc[j];
                float2 f2 = __bfloat1622float2(ep[(size_t)j*(HH/2)]);
                ax = fmaf(wj, f2.x, ax);
                ay = fmaf(wj, f2.y, ay);
            }
            float2* outp = reinterpret_cast<float2*>(d_ctxp + (size_t)c*BB*HH + (size_t)b*HH) + tid;
            *outp = make_float2(ax, ay);
            __syncthreads();
        }
        gsync();

        // ===== P4: GRU mm partials for gi0 (ctx-merge), gh0, gh1 (K-split 4) =====
        for (int u = bid; u < 1152; u += GPB){
            int which = u / 384;         // 0 gi0, 1 gh0, 2 gh1
            int rr = u - which*384;
            int kc = rr / 96;
            int n0 = (rr - kc*96) * 16;
            const float* Aa = nullptr; const float* Bw; int ldb;
            if (which == 0){ Bw = Wih0 + EE; ldb = EE + HH; }
            else if (which == 1){ Aa = d_h0[cur]; Bw = Whh0; ldb = HH; }
            else { Aa = d_h1[cur]; Bw = Whh1; ldb = HH; }
            float* C = d_gp[which][kc];

            float (*As)[68] = reinterpret_cast<float(*)[68]>(sbuf);
            float (*Bs)[20] = reinterpret_cast<float(*)[20]>(sbuf + 16*68);
            int ty = tid >> 4, tx = tid & 15;
            int tm0 = ty*4;
            int arow = tid >> 2, akc = (tid & 3) << 2;
            float acc0=0.f, acc1=0.f, acc2=0.f, acc3=0.f;

            for (int k0 = kc*128; k0 < kc*128 + 128; k0 += 16){
                float4 av;
                if (which == 0){
                    const float* p = d_ctxp + (size_t)arow*HH + k0 + akc;
                    float4 a0 = *reinterpret_cast<const float4*>(p);
                    float4 a1 = *reinterpret_cast<const float4*>(p + BB*HH);
                    float4 a2 = *reinterpret_cast<const float4*>(p + 2*BB*HH);
                    float4 a3 = *reinterpret_cast<const float4*>(p + 3*BB*HH);
                    av.x = a0.x+a1.x+a2.x+a3.x; av.y = a0.y+a1.y+a2.y+a3.y;
                    av.z = a0.z+a1.z+a2.z+a3.z; av.w = a0.w+a1.w+a2.w+a3.w;
                } else {
                    av = *reinterpret_cast<const float4*>(Aa + (size_t)arow*HH + k0 + akc);
                }
                As[akc+0][arow]=av.x; As[akc+1][arow]=av.y; As[akc+2][arow]=av.z; As[akc+3][arow]=av.w;
                if (tid < 64){
                    float4 bv = *reinterpret_cast<const float4*>(Bw + (size_t)(n0 + arow)*ldb + k0 + akc);
                    Bs[akc+0][arow]=bv.x; Bs[akc+1][arow]=bv.y; Bs[akc+2][arow]=bv.z; Bs[akc+3][arow]=bv.w;
                }
                __syncthreads();
                #pragma unroll
                for (int kk=0; kk<16; kk++){
                    float4 a = *reinterpret_cast<const float4*>(&As[kk][tm0]);
                    float bv = Bs[kk][tx];
                    acc0 = fmaf(a.x, bv, acc0);
                    acc1 = fmaf(a.y, bv, acc1);
                    acc2 = fmaf(a.z, bv, acc2);
                    acc3 = fmaf(a.w, bv, acc3);
                }
                __syncthreads();
            }
            int n = n0 + tx;
            C[(size_t)(tm0+0)*(3*HH) + n] = acc0;
            C[(size_t)(tm0+1)*(3*HH) + n] = acc1;
            C[(size_t)(tm0+2)*(3*HH) + n] = acc2;
            C[(size_t)(tm0+3)*(3*HH) + n] = acc3;
        }
        gsync();

        // ===== P5: gates layer 0 (merge 4 partials + giEmb / bhh0) =====
        if (bid < 128){
            int idx = bid*256 + tid;
            int b = idx >> 9, j = idx & 511;
            size_t o = (size_t)b*3*HH + j;
            const float* ge = d_giEmb + (size_t)s*BB*3*HH;
            float gir = d_gp[0][0][o] + d_gp[0][1][o] + d_gp[0][2][o] + d_gp[0][3][o] + ge[o];
            float ghr = d_gp[1][0][o] + d_gp[1][1][o] + d_gp[1][2][o] + d_gp[1][3][o] + bhh0[j];
            size_t o1 = o + HH;
            float giz = d_gp[0][0][o1] + d_gp[0][1][o1] + d_gp[0][2][o1] + d_gp[0][3][o1] + ge[o1];
            float ghz = d_gp[1][0][o1] + d_gp[1][1][o1] + d_gp[1][2][o1] + d_gp[1][3][o1] + bhh0[j+HH];
            size_t o2 = o + 2*HH;
            float gin = d_gp[0][0][o2] + d_gp[0][1][o2] + d_gp[0][2][o2] + d_gp[0][3][o2] + ge[o2];
            float ghn = d_gp[1][0][o2] + d_gp[1][1][o2] + d_gp[1][2][o2] + d_gp[1][3][o2] + bhh0[j+2*HH];
            float r = sigm(gir + ghr);
            float z = sigm(giz + ghz);
            float n = tanhf(gin + r*ghn);
            d_h0[cur^1][idx] = (1.0f - z)*n + z*d_h0[cur][idx];
        }
        gsync();

        // ===== P6: GRU mm partials for gi1 (A = h0 new) =====
        for (int u = bid; u < 384; u += GPB){
            int kc = u / 96;
            int n0 = (u - kc*96) * 16;
            const float* Aa = d_h0[cur^1];
            const float* Bw = Wih1;
            float* C = d_gp[3][kc];

            float (*As)[68] = reinterpret_cast<float(*)[68]>(sbuf);
            float (*Bs)[20] = reinterpret_cast<float(*)[20]>(sbuf + 16*68);
            int ty = tid >> 4, tx = tid & 15;
            int tm0 = ty*4;
            int arow = tid >> 2, akc = (tid & 3) << 2;
            float acc0=0.f, acc1=0.f, acc2=0.f, acc3=0.f;

            for (int k0 = kc*128; k0 < kc*128 + 128; k0 += 16){
                float4 av = *reinterpret_cast<const float4*>(Aa + (size_t)arow*HH + k0 + akc);
                As[akc+0][arow]=av.x; As[akc+1][arow]=av.y; As[akc+2][arow]=av.z; As[akc+3][arow]=av.w;
                if (tid < 64){
                    float4 bv = *reinterpret_cast<const float4*>(Bw + (size_t)(n0 + arow)*HH + k0 + akc);
                    Bs[akc+0][arow]=bv.x; Bs[akc+1][arow]=bv.y; Bs[akc+2][arow]=bv.z; Bs[akc+3][arow]=bv.w;
                }
                __syncthreads();
                #pragma unroll
                for (int kk=0; kk<16; kk++){
                    float4 a = *reinterpret_cast<const float4*>(&As[kk][tm0]);
                    float bv = Bs[kk][tx];
                    acc0 = fmaf(a.x, bv, acc0);
                    acc1 = fmaf(a.y, bv, acc1);
                    acc2 = fmaf(a.z, bv, acc2);
                    acc3 = fmaf(a.w, bv, acc3);
                }
                __syncthreads();
            }
            int n = n0 + tx;
            C[(size_t)(tm0+0)*(3*HH) + n] = acc0;
            C[(size_t)(tm0+1)*(3*HH) + n] = acc1;
            C[(size_t)(tm0+2)*(3*HH) + n] = acc2;
            C[(size_t)(tm0+3)*(3*HH) + n] = acc3;
        }
        gsync();

        // ===== P7: gates layer 1 (gi from gp[3]+bih1, gh from gp[2]+bhh1) =====
        if (bid < 128){
            int idx = bid*256 + tid;
            int b = idx >> 9, j = idx & 511;
            size_t o = (size_t)b*3*HH + j;
            float gir = d_gp[3][0][o] + d_gp[3][1][o] + d_gp[3][2][o] + d_gp[3][3][o] + bih1[j];
            float ghr = d_gp[2][0][o] + d_gp[2][1][o] + d_gp[2][2][o] + d_gp[2][3][o] + bhh1[j];
            size_t o1 = o + HH;
            float giz = d_gp[3][0][o1] + d_gp[3][1][o1] + d_gp[3][2][o1] + d_gp[3][3][o1] + bih1[j+HH];
            float ghz = d_gp[2][0][o1] + d_gp[2][1][o1] + d_gp[2][2][o1] + d_gp[2][3][o1] + bhh1[j+HH];
            size_t o2 = o + 2*HH;
            float gin = d_gp[3][0][o2] + d_gp[3][1][o2] + d_gp[3][2][o2] + d_gp[3][3][o2] + bih1[j+2*HH];
            float ghn = d_gp[2][0][o2] + d_gp[2][1][o2] + d_gp[2][2][o2] + d_gp[2][3][o2] + bhh1[j+2*HH];
            float r = sigm(gir + ghr);
            float z = sigm(giz + ghz);
            float n = tanhf(gin + r*ghn);
            float hv = (1.0f - z)*n + z*d_h1[cur][idx];
            d_h1[cur^1][idx] = hv;
            d_hstates[(size_t)s*BB*HH + idx] = hv;
        }
        gsync();
    }
}

// ------------------------- launch -------------------------
extern "C" void kernel_launch(void* const* d_in, const int* in_sizes, int n_in,
                              void* d_out, int out_size){
    const float* enc = (const float*)d_in[0];
    const float* efs = (const float*)d_in[1];
    const int*   tgt = (const int*)  d_in[2];
    const float* Qw  = (const float*)d_in[3];
    const float* Qb  = (const float*)d_in[4];
    const float* Kw  = (const float*)d_in[5];
    const float* Kb  = (const float*)d_in[6];
    const float* Vw  = (const float*)d_in[7];
    const float* Vb  = (const float*)d_in[8];
    const float* emb = (const float*)d_in[9];
    const float* Wih0= (const float*)d_in[10];
    const float* Whh0= (const float*)d_in[11];
    const float* bih0= (const float*)d_in[12];
    const float* bhh0= (const float*)d_in[13];
    const float* Wih1= (const float*)d_in[14];
    const float* Whh1= (const float*)d_in[15];
    const float* bih1= (const float*)d_in[16];
    const float* bhh1= (const float*)d_in[17];
    const float* Pw  = (const float*)d_in[18];
    const float* Pb  = (const float*)d_in[19];
    float* out = (float*)d_out;

    float *p_xemb, *p_giEmb, *p_kproj, *p_hstates;
    cudaGetSymbolAddress((void**)&p_xemb,    d_xemb);
    cudaGetSymbolAddress((void**)&p_giEmb,   d_giEmb);
    cudaGetSymbolAddress((void**)&p_kproj,   d_kproj);
    cudaGetSymbolAddress((void**)&p_hstates, d_hstates);

    // one-time precomputation
    k_init<<<(BB*HH + 255)/256, 256>>>(efs);
    k_embed<<<SS*BB, 128>>>(tgt, emb);
    k_enc2bf<<<LTD, 256>>>(enc);
    {   // gi_emb[s,b,:] = relu(emb) @ Wih0[:, :EE]^T + bih0
        dim3 g(SS*BB/128, (3*HH)/64, 1);
        k_sgemm<false><<<g, 256>>>(p_xemb, EE, 0, Wih0, EE+HH, 0, bih0, 0,
                                   p_giEmb, 3*HH, 0, SS*BB, 3*HH, EE);
    }
    {   // kproj[l,t,b,:] = enc @ Kw[l]^T + Kb[l]
        dim3 g(TT*BB/128, (AT+63)/64, LL);
        k_sgemm<false><<<g, 256>>>(enc, HH, (long long)TT*BB*HH,
                                   Kw, HH, (long long)AT*HH,
                                   Kb, AT,
                                   p_kproj, AT, (long long)TT*BB*AT,
                                   TT*BB, AT, HH);
    }
    k_kproj2bf<<<6400, 256>>>();

    // entire sequential decode loop in ONE persistent kernel
    k_decode_loop<<<GPB, 256>>>(Qw, Qb, Vw, Vb,
                                Wih0, Whh0, bhh0,
                                Wih1, bih1, Whh1, bhh1);

    {   // deferred output projection: logits = hstates @ Pw^T + Pb, permuted to (B,S,V)
        dim3 g(SS*BB/128, (VV+63)/64, 1);
        k_sgemm<true><<<g, 256>>>(p_hstates, HH, 0, Pw, HH, 0, Pb, 0,
                                  out, VV, 0, SS*BB, VV, HH);
    }
}

// round 13
// speedup vs baseline: 1.0974x; 1.0974x over previous
#include <cuda_runtime.h>
#include <cuda_bf16.h>
#include <math.h>
#include <string.h>

#define LL 2
#define TT 512
#define BB 64
#define HH 512
#define AT 200
#define EE 512
#define VV 10000
#define SS 128
#define LTD (LL*TT)   // 1024

// ------------------------- scratch (static device memory) -------------------------
__device__ float d_kproj[(size_t)LL*TT*BB*AT];            // fp32 GEMM out
__device__ __nv_bfloat16 d_kprojh[(size_t)LL*TT*BB*AT];   // bf16 copy (26 MB)
__device__ __nv_bfloat16 d_ench[(size_t)BB*LTD*HH];       // enc transposed (b,lt,h) bf16 (67 MB)
__device__ float d_xemb [(size_t)SS*BB*EE];
__device__ float d_giEmb[(size_t)SS*BB*3*HH];
__device__ float d_hstates[(size_t)SS*BB*HH];
__device__ float d_h0[2][BB*HH];
__device__ float d_h1[2][BB*HH];
__device__ float d_q[LL*BB*AT];
__device__ float d_ctx[BB*HH];
__device__ float d_gh0[BB*3*HH];
__device__ float d_gh1[BB*3*HH];

__device__ __forceinline__ float sigm(float x){ return 1.0f/(1.0f + __expf(-x)); }
__device__ __forceinline__ float tanh_fast(float x){
    float y; asm("tanh.approx.f32 %0, %1;" : "=f"(y) : "f"(x)); return y;
}

// packed fp32x2 fma (sm_103a)
__device__ __forceinline__ float2 ffma2(float2 a, float2 b, float2 c){
    unsigned long long ua, ub, uc, ud;
    memcpy(&ua, &a, 8); memcpy(&ub, &b, 8); memcpy(&uc, &c, 8);
    asm("fma.rn.f32x2 %0, %1, %2, %3;" : "=l"(ud) : "l"(ua), "l"(ub), "l"(uc));
    float2 d; memcpy(&d, &ud, 8);
    return d;
}

// ------------------------- init h from encoder_final_states -------------------------
__global__ void k_init(const float* __restrict__ efs){
    int i = blockIdx.x*blockDim.x + threadIdx.x;
    if (i < BB*HH){ d_h0[0][i] = efs[i]; d_h1[0][i] = efs[BB*HH + i]; }
}

// ------------------------- embedding + relu for all steps -------------------------
__global__ void k_embed(const int* __restrict__ tgt, const float* __restrict__ emb){
    int sb = blockIdx.x;           // s*BB + b
    int s = sb / BB, b = sb % BB;
    int tok = (s == 0) ? 0 : tgt[b*SS + (s-1)];
    const float4* src = reinterpret_cast<const float4*>(emb + (size_t)tok*EE);
    float4* dst = reinterpret_cast<float4*>(d_xemb + (size_t)sb*EE);
    float4 v = src[threadIdx.x];
    v.x = fmaxf(v.x, 0.f); v.y = fmaxf(v.y, 0.f); v.z = fmaxf(v.z, 0.f); v.w = fmaxf(v.w, 0.f);
    dst[threadIdx.x] = v;
}

// ------------------------- bf16 converts (once) -------------------------
__global__ void k_kproj2bf(){
    size_t n2 = (size_t)LL*TT*BB*AT/2;
    for (size_t i = blockIdx.x*(size_t)blockDim.x + threadIdx.x; i < n2; i += (size_t)gridDim.x*blockDim.x){
        float2 v = reinterpret_cast<const float2*>(d_kproj)[i];
        reinterpret_cast<__nv_bfloat162*>(d_kprojh)[i] = __floats2bfloat162_rn(v.x, v.y);
    }
}
__global__ void k_enc2bf(const float* __restrict__ enc){
    int lt = blockIdx.x;   // 1024
    int tid = threadIdx.x; // 256
    for (int b = 0; b < BB; b++){
        float2 v = *reinterpret_cast<const float2*>(enc + ((size_t)lt*BB + b)*HH + 2*tid);
        reinterpret_cast<__nv_bfloat162*>(d_ench + ((size_t)b*LTD + lt)*HH)[tid] =
            __floats2bfloat162_rn(v.x, v.y);
    }
}

// ------------------------- generic fp32 NT-GEMM with f32x2 inner loop -------------------------
template<bool PERM>
__global__ void __launch_bounds__(256) k_sgemm(
    const float* __restrict__ Ag, int lda, long long strideA,
    const float* __restrict__ Bg, int ldb, long long strideB,
    const float* __restrict__ bias, int strideBias,
    float* __restrict__ Cg, int ldc, long long strideC,
    int M, int N, int K)
{
    int z = blockIdx.z;
    const float* A  = Ag + (size_t)z*strideA;
    const float* Bw = Bg + (size_t)z*strideB;
    float* C = Cg + (size_t)z*strideC;
    const float* bi = bias ? (bias + (size_t)z*strideBias) : nullptr;

    __shared__ float As[16][132];
    __shared__ float Bs[16][68];

    int m0 = blockIdx.x*128, n0 = blockIdx.y*64;
    int tid = threadIdx.x;
    int ty = tid >> 4, tx = tid & 15;

    float2 acc2[4][4];    // [m-pair][n], pairs along m
    #pragma unroll
    for (int i=0;i<4;i++)
        #pragma unroll
        for (int j=0;j<4;j++) acc2[i][j] = make_float2(0.f, 0.f);

    for (int k0 = 0; k0 < K; k0 += 16){
        #pragma unroll
        for (int r=0;r<2;r++){
            int id = tid + r*256;
            int row = id >> 2, kc = (id & 3) << 2;
            float4 v = *reinterpret_cast<const float4*>(A + (size_t)(m0+row)*lda + k0 + kc);
            As[kc+0][row]=v.x; As[kc+1][row]=v.y; As[kc+2][row]=v.z; As[kc+3][row]=v.w;
        }
        {
            int row = tid >> 2, kc = (tid & 3) << 2;
            float4 v = make_float4(0.f,0.f,0.f,0.f);
            if (n0 + row < N)
                v = *reinterpret_cast<const float4*>(Bw + (size_t)(n0+row)*ldb + k0 + kc);
            Bs[kc+0][row]=v.x; Bs[kc+1][row]=v.y; Bs[kc+2][row]=v.z; Bs[kc+3][row]=v.w;
        }
        __syncthreads();
        #pragma unroll
        for (int kk=0; kk<16; kk++){
            const float2* ap2 = reinterpret_cast<const float2*>(&As[kk][ty*8]);
            float2 ap[4] = {ap2[0], ap2[1], ap2[2], ap2[3]};
            float4 b4 = *reinterpret_cast<const float4*>(&Bs[kk][tx*4]);
            float2 bd[4] = {make_float2(b4.x,b4.x), make_float2(b4.y,b4.y),
                            make_float2(b4.z,b4.z), make_float2(b4.w,b4.w)};
            #pragma unroll
            for (int i=0;i<4;i++)
                #pragma unroll
                for (int j=0;j<4;j++)
                    acc2[i][j] = ffma2(ap[i], bd[j], acc2[i][j]);
        }
        __syncthreads();
    }

    #pragma unroll
    for (int i=0;i<4;i++){
        #pragma unroll
        for (int j=0;j<4;j++){
            int n = n0 + tx*4 + j;
            if (n < N){
                float add = bi ? bi[n] : 0.f;
                float vx = acc2[i][j].x + add;
                float vy = acc2[i][j].y + add;
                int mx = m0 + ty*8 + i*2;
                if (PERM){
                    int srow = mx >> 6, brow = mx & 63;
                    C[((size_t)brow*SS + srow)*VV + n] = vx;
                    int my = mx + 1;
                    srow = my >> 6; brow = my & 63;
                    C[((size_t)brow*SS + srow)*VV + n] = vy;
                } else {
                    C[(size_t)mx*ldc + n] = vx;
                    C[(size_t)(mx+1)*ldc + n] = vy;
                }
            }
        }
    }
}

// =================== step node 1: front = q + gh0 + gh1 ===================
// blocks 0..3199: q warp-per-output; 3200..3295: gh0; 3296..3391: gh1
__global__ void __launch_bounds__(256) k_front(
    const float* __restrict__ Qw, const float* __restrict__ Qb,
    const float* __restrict__ Whh0, const float* __restrict__ Whh1, int cur)
{
    __shared__ float As[16][68];
    __shared__ float Bs[16][20];
    int bid = blockIdx.x, tid = threadIdx.x;

    if (bid < 3200){
        int gw = (bid*256 + tid) >> 5;
        int lane = tid & 31;
        int l = gw / (BB*AT);
        int rem = gw - l*(BB*AT);
        int b = rem / AT;
        int a = rem - b*AT;
        const float4* hr = reinterpret_cast<const float4*>((l==0 ? d_h0[cur] : d_h1[cur]) + (size_t)b*HH);
        const float4* wr = reinterpret_cast<const float4*>(Qw + (size_t)(l*AT + a)*HH);
        float sum = 0.f;
        #pragma unroll
        for (int i=0;i<4;i++){
            float4 h4 = hr[lane + i*32];
            float4 w4 = wr[lane + i*32];
            sum += h4.x*w4.x + h4.y*w4.y + h4.z*w4.z + h4.w*w4.w;
        }
        #pragma unroll
        for (int off=16; off; off>>=1) sum += __shfl_xor_sync(0xffffffffu, sum, off);
        if (lane == 0) d_q[gw] = sum + Qb[l*AT + a];
        return;
    }

    // gh role
    int r = bid - 3200;
    int mode1 = r >= 96;                 // 0: gh0, 1: gh1
    int n0 = (r % 96) * 16;
    const float* Aa = mode1 ? d_h1[cur] : d_h0[cur];
    const float* Bw = mode1 ? Whh1 : Whh0;
    float* C = mode1 ? d_gh1 : d_gh0;

    int ty = tid >> 4, tx = tid & 15;
    int tm0 = ty*4;
    int arow = tid >> 2, akc = (tid & 3) << 2;
    float acc0=0.f, acc1=0.f, acc2=0.f, acc3=0.f;

    for (int k0=0; k0<HH; k0+=16){
        float4 av = *reinterpret_cast<const float4*>(Aa + (size_t)arow*HH + k0 + akc);
        As[akc+0][arow]=av.x; As[akc+1][arow]=av.y; As[akc+2][arow]=av.z; As[akc+3][arow]=av.w;
        if (tid < 64){
            float4 bv = *reinterpret_cast<const float4*>(Bw + (size_t)(n0 + arow)*HH + k0 + akc);
            Bs[akc+0][arow]=bv.x; Bs[akc+1][arow]=bv.y; Bs[akc+2][arow]=bv.z; Bs[akc+3][arow]=bv.w;
        }
        __syncthreads();
        #pragma unroll
        for (int kk=0; kk<16; kk++){
            float4 a = *reinterpret_cast<const float4*>(&As[kk][tm0]);
            float bv = Bs[kk][tx];
            acc0 = fmaf(a.x, bv, acc0);
            acc1 = fmaf(a.y, bv, acc1);
            acc2 = fmaf(a.z, bv, acc2);
            acc3 = fmaf(a.w, bv, acc3);
        }
        __syncthreads();
    }
    int n = n0 + tx;
    C[(size_t)(tm0+0)*(3*HH) + n] = acc0;
    C[(size_t)(tm0+1)*(3*HH) + n] = acc1;
    C[(size_t)(tm0+2)*(3*HH) + n] = acc2;
    C[(size_t)(tm0+3)*(3*HH) + n] = acc3;
}

// =================== step node 2: scores + softmax + context ===================
// grid (BB, 2), 512 threads. Block computes all 1024 scores for b (into smem),
// softmax, then context for its half of h (256 cols).
__global__ void __launch_bounds__(512) k_att(const float* __restrict__ Vw, const float* __restrict__ Vb){
    __shared__ float sw[LTD];
    __shared__ float red[16];
    __shared__ float comb[256];
    int b = blockIdx.x, half = blockIdx.y;
    int tid = threadIdx.x;
    int w = tid >> 5, lane = tid & 31;

    // ---- scores: warp w handles 64 lt rows [w*64, w*64+64) ----
    {
        int l = w >> 3;
        float q8[8], v8[8];
        if (lane < 25){
            const float4* qp = reinterpret_cast<const float4*>(d_q + (size_t)(l*BB + b)*AT + lane*8);
            const float4* vp = reinterpret_cast<const float4*>(Vw + l*AT + lane*8);
            float4 a = qp[0], c = qp[1], e = vp[0], f = vp[1];
            q8[0]=a.x;q8[1]=a.y;q8[2]=a.z;q8[3]=a.w;q8[4]=c.x;q8[5]=c.y;q8[6]=c.z;q8[7]=c.w;
            v8[0]=e.x;v8[1]=e.y;v8[2]=e.z;v8[3]=e.w;v8[4]=f.x;v8[5]=f.y;v8[6]=f.z;v8[7]=f.w;
        } else {
            #pragma unroll
            for (int i=0;i<8;i++){ q8[i]=0.f; v8[i]=0.f; }
        }
        float vb = Vb[l];
        const uint4* kp = reinterpret_cast<const uint4*>(d_kprojh);
        int lt0 = w*64;
        size_t base = ((size_t)lt0*BB + b)*25 + lane;
        uint4 c0 = make_uint4(0,0,0,0), c1 = c0;
        if (lane < 25){ c0 = kp[base]; c1 = kp[base + (size_t)BB*25]; }
        #pragma unroll 4
        for (int r=0;r<64;r++){
            uint4 nx = make_uint4(0,0,0,0);
            if (r+2 < 64 && lane < 25) nx = kp[base + (size_t)(r+2)*BB*25];
            const __nv_bfloat162* p = reinterpret_cast<const __nv_bfloat162*>(&c0);
            float sum = 0.f;
            #pragma unroll
            for (int j=0;j<4;j++){
                float2 f2 = __bfloat1622float2(p[j]);
                sum = fmaf(v8[2*j+0], tanh_fast(f2.x + q8[2*j+0]), sum);
                sum = fmaf(v8[2*j+1], tanh_fast(f2.y + q8[2*j+1]), sum);
            }
            #pragma unroll
            for (int off=16; off; off>>=1) sum += __shfl_xor_sync(0xffffffffu, sum, off);
            if (lane == 0) sw[lt0 + r] = sum + vb;
            c0 = c1; c1 = nx;
        }
    }
    __syncthreads();

    // ---- softmax over sw[1024] ----
    {
        float v0 = sw[tid], v1 = sw[tid + 512];
        float mx = fmaxf(v0, v1);
        #pragma unroll
        for (int off=16; off; off>>=1) mx = fmaxf(mx, __shfl_xor_sync(0xffffffffu, mx, off));
        if (lane == 0) red[w] = mx;
        __syncthreads();
        float m = red[0];
        #pragma unroll
        for (int i=1;i<16;i++) m = fmaxf(m, red[i]);
        float e0 = __expf(v0 - m), e1 = __expf(v1 - m);
        float se = e0 + e1;
        #pragma unroll
        for (int off=16; off; off>>=1) se += __shfl_xor_sync(0xffffffffu, se, off);
        __syncthreads();
        if (lane == 0) red[w] = se;
        __syncthreads();
        float tot = red[0];
        #pragma unroll
        for (int i=1;i<16;i++) tot += red[i];
        float inv = 1.0f / tot;
        sw[tid] = e0 * inv;
        sw[tid + 512] = e1 * inv;
    }
    __syncthreads();

    // ---- context for h half: thread owns one h col, half the lt range ----
    {
        int hc = half*256 + (tid & 255);
        int ltp = tid >> 8;                 // 0 or 1
        const __nv_bfloat16* ep = d_ench + ((size_t)b*LTD + ltp*512)*HH + hc;
        const float* wc = &sw[ltp*512];
        float acc = 0.f;
        #pragma unroll 16
        for (int j=0;j<512;j++)
            acc = fmaf(wc[j], __bfloat162float(ep[(size_t)j*HH]), acc);
        if (ltp == 1){ comb[tid & 255] = acc; }
        __syncthreads();
        if (ltp == 0) d_ctx[(size_t)b*HH + hc] = acc + comb[tid];
    }
}

// =================== step nodes 3/4: GRU layer GEMM + fused gates ===================
// 64 blocks, 256 threads. Block owns j-slice of 8; computes gi for r/z/n columns
// (24 rows of B) then applies the gate nonlinearity as epilogue.
// layer 0: A=d_ctx, B=Wih0[:,EE:], gi_extra=giEmb[s], gh=d_gh0+bhh0, h=h0 -> h0new
// layer 1: A=h0new,  B=Wih1,        gi_extra=bih1,     gh=d_gh1+bhh1, h=h1 -> h1new,+hstates
__global__ void __launch_bounds__(256) k_layer(
    int layer, int cur, int s,
    const float* __restrict__ Wih0, const float* __restrict__ Wih1,
    const float* __restrict__ bih1,
    const float* __restrict__ bhh0, const float* __restrict__ bhh1)
{
    __shared__ float As[16][68];
    __shared__ float Bs[16][28];
    int tid = threadIdx.x;
    int j0 = blockIdx.x*8;

    const float* Aa  = layer ? d_h0[cur^1] : d_ctx;
    const float* Bw  = layer ? Wih1 : (Wih0 + EE);
    int ldb          = layer ? HH : (EE + HH);
    const float* gh  = layer ? d_gh1 : d_gh0;
    const float* bhh = layer ? bhh1 : bhh0;
    const float* hold= layer ? d_h1[cur] : d_h0[cur];

    int arow = tid >> 2, akc = (tid & 3) << 2;
    int brow = tid >> 2, bkc = (tid & 3) << 2;   // brow<24 used
    int ty = tid >> 3, tx = tid & 7;             // ty: m-pair 0..31, tx: j 0..7
    float2 accr = make_float2(0.f,0.f), accz = accr, accn = accr;

    for (int k0=0; k0<HH; k0+=16){
        {
            float4 av = *reinterpret_cast<const float4*>(Aa + (size_t)arow*HH + k0 + akc);
            As[akc+0][arow]=av.x; As[akc+1][arow]=av.y; As[akc+2][arow]=av.z; As[akc+3][arow]=av.w;
        }
        if (tid < 96){
            int g = brow >> 3, jj = brow & 7;
            int nrow = g*HH + j0 + jj;
            float4 bv = *reinterpret_cast<const float4*>(Bw + (size_t)nrow*ldb + k0 + bkc);
            Bs[bkc+0][brow]=bv.x; Bs[bkc+1][brow]=bv.y; Bs[bkc+2][brow]=bv.z; Bs[bkc+3][brow]=bv.w;
        }
        __syncthreads();
        #pragma unroll
        for (int kk=0; kk<16; kk++){
            float2 ap = *reinterpret_cast<const float2*>(&As[kk][ty*2]);
            float br = Bs[kk][tx], bz = Bs[kk][8+tx], bn = Bs[kk][16+tx];
            accr = ffma2(ap, make_float2(br,br), accr);
            accz = ffma2(ap, make_float2(bz,bz), accz);
            accn = ffma2(ap, make_float2(bn,bn), accn);
        }
        __syncthreads();
    }

    // fused gates epilogue: thread owns (b = ty*2, ty*2+1) x (j = j0+tx)
    int j = j0 + tx;
    float bh_r = bhh[j], bh_z = bhh[j+HH], bh_n = bhh[j+2*HH];
    float bi_r, bi_z, bi_n;
    const float* ge = nullptr;
    if (layer){ bi_r = bih1[j]; bi_z = bih1[j+HH]; bi_n = bih1[j+2*HH]; }
    else { ge = d_giEmb + (size_t)s*BB*3*HH; bi_r = bi_z = bi_n = 0.f; }

    #pragma unroll
    for (int i=0;i<2;i++){
        int b = ty*2 + i;
        float gr = (i==0)?accr.x:accr.y;
        float gz = (i==0)?accz.x:accz.y;
        float gn = (i==0)?accn.x:accn.y;
        size_t gb = (size_t)b*3*HH + j;
        if (!layer){ gr += ge[gb]; gz += ge[gb+HH]; gn += ge[gb+2*HH]; }
        else { gr += bi_r; gz += bi_z; gn += bi_n; }
        float r = sigm(gr + gh[gb] + bh_r);
        float z = sigm(gz + gh[gb+HH] + bh_z);
        float n = tanhf(gn + r*(gh[gb+2*HH] + bh_n));
        float hv = (1.0f - z)*n + z*hold[(size_t)b*HH + j];
        if (layer){
            d_h1[cur^1][(size_t)b*HH + j] = hv;
            d_hstates[(size_t)s*BB*HH + (size_t)b*HH + j] = hv;
        } else {
            d_h0[cur^1][(size_t)b*HH + j] = hv;
        }
    }
}

// ------------------------- launch -------------------------
extern "C" void kernel_launch(void* const* d_in, const int* in_sizes, int n_in,
                              void* d_out, int out_size){
    const float* enc = (const float*)d_in[0];
    const float* efs = (const float*)d_in[1];
    const int*   tgt = (const int*)  d_in[2];
    const float* Qw  = (const float*)d_in[3];
    const float* Qb  = (const float*)d_in[4];
    const float* Kw  = (const float*)d_in[5];
    const float* Kb  = (const float*)d_in[6];
    const float* Vw  = (const float*)d_in[7];
    const float* Vb  = (const float*)d_in[8];
    const float* emb = (const float*)d_in[9];
    const float* Wih0= (const float*)d_in[10];
    const float* Whh0= (const float*)d_in[11];
    const float* bih0= (const float*)d_in[12];
    const float* bhh0= (const float*)d_in[13];
    const float* Wih1= (const float*)d_in[14];
    const float* Whh1= (const float*)d_in[15];
    const float* bih1= (const float*)d_in[16];
    const float* bhh1= (const float*)d_in[17];
    const float* Pw  = (const float*)d_in[18];
    const float* Pb  = (const float*)d_in[19];
    float* out = (float*)d_out;

    float *p_xemb, *p_giEmb, *p_kproj, *p_hstates;
    cudaGetSymbolAddress((void**)&p_xemb,    d_xemb);
    cudaGetSymbolAddress((void**)&p_giEmb,   d_giEmb);
    cudaGetSymbolAddress((void**)&p_kproj,   d_kproj);
    cudaGetSymbolAddress((void**)&p_hstates, d_hstates);

    // one-time precomputation (single stream, graph-capturable)
    k_init<<<(BB*HH + 255)/256, 256>>>(efs);
    k_embed<<<SS*BB, 128>>>(tgt, emb);
    k_enc2bf<<<LTD, 256>>>(enc);
    {   // gi_emb[s,b,:] = relu(emb) @ Wih0[:, :EE]^T + bih0
        dim3 g(SS*BB/128, (3*HH)/64, 1);
        k_sgemm<false><<<g, 256>>>(p_xemb, EE, 0, Wih0, EE+HH, 0, bih0, 0,
                                   p_giEmb, 3*HH, 0, SS*BB, 3*HH, EE);
    }
    {   // kproj[l,t,b,:] = enc @ Kw[l]^T + Kb[l]
        dim3 g(TT*BB/128, (AT+63)/64, LL);
        k_sgemm<false><<<g, 256>>>(enc, HH, (long long)TT*BB*HH,
                                   Kw, HH, (long long)AT*HH,
                                   Kb, AT,
                                   p_kproj, AT, (long long)TT*BB*AT,
                                   TT*BB, AT, HH);
    }
    k_kproj2bf<<<6400, 256>>>();

    // sequential decode loop: 4 nodes per step
    for (int s = 0; s < SS; s++){
        int cur = s & 1;
        k_front<<<3392, 256>>>(Qw, Qb, Whh0, Whh1, cur);
        { dim3 ga(BB, 2); k_att<<<ga, 512>>>(Vw, Vb); }
        k_layer<<<64, 256>>>(0, cur, s, Wih0, Wih1, bih1, bhh0, bhh1);
        k_layer<<<64, 256>>>(1, cur, s, Wih0, Wih1, bih1, bhh0, bhh1);
    }

    {   // deferred output projection: logits = hstates @ Pw^T + Pb, permuted to (B,S,V)
        dim3 g(SS*BB/128, (VV+63)/64, 1);
        k_sgemm<true><<<g, 256>>>(p_hstates, HH, 0, Pw, HH, 0, Pb, 0,
                                  out, VV, 0, SS*BB, VV, HH);
    }
}

// round 14
// speedup vs baseline: 1.2440x; 1.1336x over previous
#include <cuda_runtime.h>
#include <cuda_bf16.h>
#include <math.h>
#include <string.h>

#define LL 2
#define TT 512
#define BB 64
#define HH 512
#define AT 200
#define EE 512
#define VV 10000
#define SS 128
#define LTD (LL*TT)   // 1024

// ------------------------- scratch (static device memory) -------------------------
__device__ float d_kproj[(size_t)LL*TT*BB*AT];            // fp32 GEMM out (unused after bf16 fold)
__device__ __nv_bfloat16 d_kprojh[(size_t)LL*TT*BB*AT];   // bf16 copy (26 MB)
__device__ __nv_bfloat16 d_ench[(size_t)BB*LTD*HH];       // enc transposed (b,lt,h) bf16 (67 MB)
__device__ float d_xemb [(size_t)SS*BB*EE];
__device__ float d_giEmb[(size_t)SS*BB*3*HH];
__device__ float d_hstates[(size_t)SS*BB*HH];
__device__ float d_h0[2][BB*HH];
__device__ float d_h1[2][BB*HH];
__device__ float d_q[LL*BB*AT];
__device__ float d_scores[BB*LTD];
__device__ float d_ctxp[4*BB*HH];                         // 4 lt-split partial contexts
__device__ float d_gi0[BB*3*HH];
__device__ float d_gh0[BB*3*HH];
__device__ float d_gi1[BB*3*HH];
__device__ float d_gh1[BB*3*HH];

__device__ __forceinline__ float sigm(float x){ return 1.0f/(1.0f + __expf(-x)); }
__device__ __forceinline__ float tanh_fast(float x){
    float y; asm("tanh.approx.f32 %0, %1;" : "=f"(y) : "f"(x)); return y;
}

// packed fp32x2 fma (sm_103a)
__device__ __forceinline__ float2 ffma2(float2 a, float2 b, float2 c){
    unsigned long long ua, ub, uc, ud;
    memcpy(&ua, &a, 8); memcpy(&ub, &b, 8); memcpy(&uc, &c, 8);
    asm("fma.rn.f32x2 %0, %1, %2, %3;" : "=l"(ud) : "l"(ua), "l"(ub), "l"(uc));
    float2 d; memcpy(&d, &ud, 8);
    return d;
}

// ------------------------- init h from encoder_final_states -------------------------
__global__ void k_init(const float* __restrict__ efs){
    int i = blockIdx.x*blockDim.x + threadIdx.x;
    if (i < BB*HH){ d_h0[0][i] = efs[i]; d_h1[0][i] = efs[BB*HH + i]; }
}

// ------------------------- embedding + relu for all steps -------------------------
__global__ void k_embed(const int* __restrict__ tgt, const float* __restrict__ emb){
    int sb = blockIdx.x;           // s*BB + b
    int s = sb / BB, b = sb % BB;
    int tok = (s == 0) ? 0 : tgt[b*SS + (s-1)];
    const float4* src = reinterpret_cast<const float4*>(emb + (size_t)tok*EE);
    float4* dst = reinterpret_cast<float4*>(d_xemb + (size_t)sb*EE);
    float4 v = src[threadIdx.x];
    v.x = fmaxf(v.x, 0.f); v.y = fmaxf(v.y, 0.f); v.z = fmaxf(v.z, 0.f); v.w = fmaxf(v.w, 0.f);
    dst[threadIdx.x] = v;
}

// ------------------------- enc bf16 transpose (once) -------------------------
__global__ void k_enc2bf(const float* __restrict__ enc){
    int lt = blockIdx.x;   // 1024
    int tid = threadIdx.x; // 256
    for (int b = 0; b < BB; b++){
        float2 v = *reinterpret_cast<const float2*>(enc + ((size_t)lt*BB + b)*HH + 2*tid);
        reinterpret_cast<__nv_bfloat162*>(d_ench + ((size_t)b*LTD + lt)*HH)[tid] =
            __floats2bfloat162_rn(v.x, v.y);
    }
}

// ------------------------- generic fp32 NT-GEMM (optional bf16 side-write) ------------------
template<bool PERM>
__global__ void __launch_bounds__(256) k_sgemm(
    const float* __restrict__ Ag, int lda, long long strideA,
    const float* __restrict__ Bg, int ldb, long long strideB,
    const float* __restrict__ bias, int strideBias,
    float* __restrict__ Cg, int ldc, long long strideC,
    __nv_bfloat16* __restrict__ Chg,
    int M, int N, int K)
{
    int z = blockIdx.z;
    const float* A  = Ag + (size_t)z*strideA;
    const float* Bw = Bg + (size_t)z*strideB;
    float* C = Cg + (size_t)z*strideC;
    __nv_bfloat16* Ch = Chg ? (Chg + (size_t)z*strideC) : nullptr;
    const float* bi = bias ? (bias + (size_t)z*strideBias) : nullptr;

    __shared__ float As[16][132];
    __shared__ float Bs[16][68];

    int m0 = blockIdx.x*128, n0 = blockIdx.y*64;
    int tid = threadIdx.x;
    int ty = tid >> 4, tx = tid & 15;

    float2 acc2[4][4];
    #pragma unroll
    for (int i=0;i<4;i++)
        #pragma unroll
        for (int j=0;j<4;j++) acc2[i][j] = make_float2(0.f, 0.f);

    for (int k0 = 0; k0 < K; k0 += 16){
        #pragma unroll
        for (int r=0;r<2;r++){
            int id = tid + r*256;
            int row = id >> 2, kc = (id & 3) << 2;
            float4 v = *reinterpret_cast<const float4*>(A + (size_t)(m0+row)*lda + k0 + kc);
            As[kc+0][row]=v.x; As[kc+1][row]=v.y; As[kc+2][row]=v.z; As[kc+3][row]=v.w;
        }
        {
            int row = tid >> 2, kc = (tid & 3) << 2;
            float4 v = make_float4(0.f,0.f,0.f,0.f);
            if (n0 + row < N)
                v = *reinterpret_cast<const float4*>(Bw + (size_t)(n0+row)*ldb + k0 + kc);
            Bs[kc+0][row]=v.x; Bs[kc+1][row]=v.y; Bs[kc+2][row]=v.z; Bs[kc+3][row]=v.w;
        }
        __syncthreads();
        #pragma unroll
        for (int kk=0; kk<16; kk++){
            const float2* ap2 = reinterpret_cast<const float2*>(&As[kk][ty*8]);
            float2 ap[4] = {ap2[0], ap2[1], ap2[2], ap2[3]};
            float4 b4 = *reinterpret_cast<const float4*>(&Bs[kk][tx*4]);
            float2 bd[4] = {make_float2(b4.x,b4.x), make_float2(b4.y,b4.y),
                            make_float2(b4.z,b4.z), make_float2(b4.w,b4.w)};
            #pragma unroll
            for (int i=0;i<4;i++)
                #pragma unroll
                for (int j=0;j<4;j++)
                    acc2[i][j] = ffma2(ap[i], bd[j], acc2[i][j]);
        }
        __syncthreads();
    }

    #pragma unroll
    for (int i=0;i<4;i++){
        #pragma unroll
        for (int j=0;j<4;j++){
            int n = n0 + tx*4 + j;
            if (n < N){
                float add = bi ? bi[n] : 0.f;
                float vx = acc2[i][j].x + add;
                float vy = acc2[i][j].y + add;
                int mx = m0 + ty*8 + i*2;
                if (PERM){
                    int srow = mx >> 6, brow = mx & 63;
                    C[((size_t)brow*SS + srow)*VV + n] = vx;
                    int my = mx + 1;
                    srow = my >> 6; brow = my & 63;
                    C[((size_t)brow*SS + srow)*VV + n] = vy;
                } else {
                    C[(size_t)mx*ldc + n] = vx;
                    C[(size_t)(mx+1)*ldc + n] = vy;
                    if (Ch){
                        Ch[(size_t)mx*ldc + n] = __float2bfloat16(vx);
                        Ch[(size_t)(mx+1)*ldc + n] = __float2bfloat16(vy);
                    }
                }
            }
        }
    }
}

// =================== step node 1: front = tiled-q (50 blocks) + gh0 (96) + gh1 (96) ===========
__global__ void __launch_bounds__(256) k_front(
    const float* __restrict__ Qw, const float* __restrict__ Qb,
    const float* __restrict__ Whh0, const float* __restrict__ Whh1, int cur)
{
    __shared__ float sbuf[4096];   // 16KB: q uses 8x512; gh aliases As/Bs
    int bid = blockIdx.x, tid = threadIdx.x;

    if (bid < 50){
        // ---- tiled q: block owns 8 global Qw rows [bid*8, bid*8+8) (rows 0..399 = l*200+a) ----
        int l = bid >= 25;
        const float4* qg = reinterpret_cast<const float4*>(Qw + (size_t)bid*8*HH);
        float4* s4 = reinterpret_cast<float4*>(sbuf);
        #pragma unroll
        for (int i=0;i<4;i++) s4[tid + i*256] = qg[tid + i*256];
        __syncthreads();
        int b = tid & 63, ap = tid >> 6;     // 4 groups x 2 rows
        const float4* hb = reinterpret_cast<const float4*>((l ? d_h1[cur] : d_h0[cur]) + (size_t)b*HH);
        const float4* w0 = reinterpret_cast<const float4*>(sbuf + (size_t)(ap*2+0)*HH);
        const float4* w1 = reinterpret_cast<const float4*>(sbuf + (size_t)(ap*2+1)*HH);
        float a0 = 0.f, a1 = 0.f;
        #pragma unroll 8
        for (int k=0;k<128;k++){
            float4 h4 = hb[k];
            float4 x0 = w0[k], x1 = w1[k];
            a0 = fmaf(h4.x,x0.x,fmaf(h4.y,x0.y,fmaf(h4.z,x0.z,fmaf(h4.w,x0.w,a0))));
            a1 = fmaf(h4.x,x1.x,fmaf(h4.y,x1.y,fmaf(h4.z,x1.z,fmaf(h4.w,x1.w,a1))));
        }
        int gr = bid*8 + ap*2;
        int a = gr - l*200;
        d_q[(size_t)(l*BB + b)*AT + a]     = a0 + Qb[gr];
        d_q[(size_t)(l*BB + b)*AT + a + 1] = a1 + Qb[gr+1];
        return;
    }

    // ---- gh role (validated k_gru1 body) ----
    int r = bid - 50;
    int mode1 = r >= 96;                 // 0: gh0, 1: gh1
    int n0 = (r % 96) * 16;
    const float* Aa = mode1 ? d_h1[cur] : d_h0[cur];
    const float* Bw = mode1 ? Whh1 : Whh0;
    float* C = mode1 ? d_gh1 : d_gh0;

    float (*As)[68] = reinterpret_cast<float(*)[68]>(sbuf);
    float (*Bs)[20] = reinterpret_cast<float(*)[20]>(sbuf + 16*68);
    int ty = tid >> 4, tx = tid & 15;
    int tm0 = ty*4;
    int arow = tid >> 2, akc = (tid & 3) << 2;
    float acc0=0.f, acc1=0.f, acc2=0.f, acc3=0.f;

    for (int k0=0; k0<HH; k0+=16){
        float4 av = *reinterpret_cast<const float4*>(Aa + (size_t)arow*HH + k0 + akc);
        As[akc+0][arow]=av.x; As[akc+1][arow]=av.y; As[akc+2][arow]=av.z; As[akc+3][arow]=av.w;
        if (tid < 64){
            float4 bv = *reinterpret_cast<const float4*>(Bw + (size_t)(n0 + arow)*HH + k0 + akc);
            Bs[akc+0][arow]=bv.x; Bs[akc+1][arow]=bv.y; Bs[akc+2][arow]=bv.z; Bs[akc+3][arow]=bv.w;
        }
        __syncthreads();
        #pragma unroll
        for (int kk=0; kk<16; kk++){
            float4 a = *reinterpret_cast<const float4*>(&As[kk][tm0]);
            float bv = Bs[kk][tx];
            acc0 = fmaf(a.x, bv, acc0);
            acc1 = fmaf(a.y, bv, acc1);
            acc2 = fmaf(a.z, bv, acc2);
            acc3 = fmaf(a.w, bv, acc3);
        }
        __syncthreads();
    }
    int n = n0 + tx;
    C[(size_t)(tm0+0)*(3*HH) + n] = acc0;
    C[(size_t)(tm0+1)*(3*HH) + n] = acc1;
    C[(size_t)(tm0+2)*(3*HH) + n] = acc2;
    C[(size_t)(tm0+3)*(3*HH) + n] = acc3;
}

// ------------------------- scores from bf16 kproj (validated R7 body) -------------------------
__global__ void __launch_bounds__(256) k_scores(const float* __restrict__ Vw, const float* __restrict__ Vb){
    int b = blockIdx.y;
    int lt0 = blockIdx.x*64;
    int l = lt0 >> 9;
    int w = threadIdx.x >> 5, lane = threadIdx.x & 31;

    float q8[8], v8[8];
    if (lane < 25){
        const float4* qp = reinterpret_cast<const float4*>(d_q + (size_t)(l*BB + b)*AT + lane*8);
        const float4* vp = reinterpret_cast<const float4*>(Vw + l*AT + lane*8);
        float4 a = qp[0], c = qp[1], e = vp[0], f = vp[1];
        q8[0]=a.x;q8[1]=a.y;q8[2]=a.z;q8[3]=a.w;q8[4]=c.x;q8[5]=c.y;q8[6]=c.z;q8[7]=c.w;
        v8[0]=e.x;v8[1]=e.y;v8[2]=e.z;v8[3]=e.w;v8[4]=f.x;v8[5]=f.y;v8[6]=f.z;v8[7]=f.w;
    } else {
        #pragma unroll
        for (int i=0;i<8;i++){ q8[i]=0.f; v8[i]=0.f; }
    }
    float vb = Vb[l];

    const uint4* kp = reinterpret_cast<const uint4*>(d_kprojh);
    int lt = lt0 + w*8;
    size_t row = ((size_t)lt*BB + b)*25;
    uint4 cur = make_uint4(0,0,0,0);
    if (lane < 25) cur = kp[row + lane];

    #pragma unroll
    for (int r=0;r<8;r++){
        uint4 nxt = make_uint4(0,0,0,0);
        if (r < 7 && lane < 25) nxt = kp[row + (size_t)(r+1)*BB*25 + lane];
        const __nv_bfloat162* p = reinterpret_cast<const __nv_bfloat162*>(&cur);
        float sum = 0.f;
        #pragma unroll
        for (int j=0;j<4;j++){
            float2 f2 = __bfloat1622float2(p[j]);
            sum = fmaf(v8[2*j+0], tanh_fast(f2.x + q8[2*j+0]), sum);
            sum = fmaf(v8[2*j+1], tanh_fast(f2.y + q8[2*j+1]), sum);
        }
        #pragma unroll
        for (int off=16; off; off>>=1) sum += __shfl_xor_sync(0xffffffffu, sum, off);
        if (lane == 0) d_scores[(size_t)b*LTD + lt + r] = sum + vb;
        cur = nxt;
    }
}

// ------------------------- fused softmax + partial context (validated R7 body) -----------------
__global__ void __launch_bounds__(256) k_ctx(){
    __shared__ float sw[LTD];
    __shared__ float red[256];
    int b = blockIdx.x, c = blockIdx.y, tid = threadIdx.x;

    float4 s4 = *reinterpret_cast<const float4*>(d_scores + (size_t)b*LTD + tid*4);
    float mx = fmaxf(fmaxf(s4.x, s4.y), fmaxf(s4.z, s4.w));
    red[tid] = mx; __syncthreads();
    for (int st=128; st>0; st>>=1){ if (tid<st) red[tid]=fmaxf(red[tid],red[tid+st]); __syncthreads(); }
    float m = red[0]; __syncthreads();
    float e0 = __expf(s4.x-m), e1 = __expf(s4.y-m), e2 = __expf(s4.z-m), e3 = __expf(s4.w-m);
    sw[tid*4+0]=e0; sw[tid*4+1]=e1; sw[tid*4+2]=e2; sw[tid*4+3]=e3;
    red[tid] = e0+e1+e2+e3; __syncthreads();
    for (int st=128; st>0; st>>=1){ if (tid<st) red[tid]+=red[tid+st]; __syncthreads(); }
    float inv = 1.0f/red[0]; __syncthreads();
    sw[c*256 + tid] *= inv;
    __syncthreads();

    const __nv_bfloat162* ep = reinterpret_cast<const __nv_bfloat162*>(d_ench) +
                               ((size_t)b*LTD + c*256)*(HH/2) + tid;
    const float* wc = &sw[c*256];
    float ax = 0.f, ay = 0.f;
    #pragma unroll 16
    for (int j=0;j<256;j++){
        float wj = wc[j];
        float2 f2 = __bfloat1622float2(ep[(size_t)j*(HH/2)]);
        ax = fmaf(wj, f2.x, ax);
        ay = fmaf(wj, f2.y, ay);
    }
    float2* outp = reinterpret_cast<float2*>(d_ctxp + (size_t)c*BB*HH + (size_t)b*HH) + tid;
    *outp = make_float2(ax, ay);
}

// ------------------------- gi GEMM (modes 0: gi0 ctx-merge, 2: gi1) ------------------------
__global__ void __launch_bounds__(256) k_gru1(
    int mode, int cur,
    const float* __restrict__ Wih0, const float* __restrict__ Wih1)
{
    const float* Aa = nullptr; const float* Bw; int ldb; float* C;
    bool merge = false;
    if (mode == 0){ merge = true;      Bw = Wih0 + EE; ldb = EE + HH; C = d_gi0; }
    else          { Aa = d_h0[cur^1];  Bw = Wih1;      ldb = HH;      C = d_gi1; }

    __shared__ float As[16][68];
    __shared__ float Bs[16][20];
    int tid = threadIdx.x;
    int n0 = blockIdx.x*16;
    int ty = tid >> 4, tx = tid & 15;
    int tm0 = ty*4;
    int arow = tid >> 2, akc = (tid & 3) << 2;
    float acc0=0.f, acc1=0.f, acc2=0.f, acc3=0.f;

    for (int k0=0; k0<HH; k0+=16){
        float4 av;
        if (merge){
            const float* p = d_ctxp + (size_t)arow*HH + k0 + akc;
            float4 a0 = *reinterpret_cast<const float4*>(p);
            float4 a1 = *reinterpret_cast<const float4*>(p + BB*HH);
            float4 a2 = *reinterpret_cast<const float4*>(p + 2*BB*HH);
            float4 a3 = *reinterpret_cast<const float4*>(p + 3*BB*HH);
            av.x = a0.x+a1.x+a2.x+a3.x; av.y = a0.y+a1.y+a2.y+a3.y;
            av.z = a0.z+a1.z+a2.z+a3.z; av.w = a0.w+a1.w+a2.w+a3.w;
        } else {
            av = *reinterpret_cast<const float4*>(Aa + (size_t)arow*HH + k0 + akc);
        }
        As[akc+0][arow]=av.x; As[akc+1][arow]=av.y; As[akc+2][arow]=av.z; As[akc+3][arow]=av.w;
        if (tid < 64){
            float4 bv = *reinterpret_cast<const float4*>(Bw + (size_t)(n0 + arow)*ldb + k0 + akc);
            Bs[akc+0][arow]=bv.x; Bs[akc+1][arow]=bv.y; Bs[akc+2][arow]=bv.z; Bs[akc+3][arow]=bv.w;
        }
        __syncthreads();
        #pragma unroll
        for (int kk=0; kk<16; kk++){
            float4 a = *reinterpret_cast<const float4*>(&As[kk][tm0]);
            float bv = Bs[kk][tx];
            acc0 = fmaf(a.x, bv, acc0);
            acc1 = fmaf(a.y, bv, acc1);
            acc2 = fmaf(a.z, bv, acc2);
            acc3 = fmaf(a.w, bv, acc3);
        }
        __syncthreads();
    }
    int n = n0 + tx;
    C[(size_t)(tm0+0)*(3*HH) + n] = acc0;
    C[(size_t)(tm0+1)*(3*HH) + n] = acc1;
    C[(size_t)(tm0+2)*(3*HH) + n] = acc2;
    C[(size_t)(tm0+3)*(3*HH) + n] = acc3;
}

// ------------------------- GRU gates (validated R11 bodies) -------------------------
__global__ void k_gates0(int cur, int s, const float* __restrict__ bhh0){
    int idx = blockIdx.x*256 + threadIdx.x;       // BB*HH
    int b = idx >> 9, j = idx & 511;
    const float* gi = d_gi0 + (size_t)b*3*HH;
    const float* gh = d_gh0 + (size_t)b*3*HH;
    const float* ge = d_giEmb + (size_t)s*BB*3*HH + (size_t)b*3*HH;
    float r = sigm(gi[j] + ge[j] + gh[j] + bhh0[j]);
    float z = sigm(gi[j+HH] + ge[j+HH] + gh[j+HH] + bhh0[j+HH]);
    float n = tanhf(gi[j+2*HH] + ge[j+2*HH] + r*(gh[j+2*HH] + bhh0[j+2*HH]));
    d_h0[cur^1][idx] = (1.0f - z)*n + z*d_h0[cur][idx];
}
__global__ void k_gates1(int cur, int s, const float* __restrict__ bih1, const float* __restrict__ bhh1){
    int idx = blockIdx.x*256 + threadIdx.x;
    int b = idx >> 9, j = idx & 511;
    const float* gi = d_gi1 + (size_t)b*3*HH;
    const float* gh = d_gh1 + (size_t)b*3*HH;
    float r = sigm(gi[j] + bih1[j] + gh[j] + bhh1[j]);
    float z = sigm(gi[j+HH] + bih1[j+HH] + gh[j+HH] + bhh1[j+HH]);
    float n = tanhf(gi[j+2*HH] + bih1[j+2*HH] + r*(gh[j+2*HH] + bhh1[j+2*HH]));
    float hv = (1.0f - z)*n + z*d_h1[cur][idx];
    d_h1[cur^1][idx] = hv;
    d_hstates[(size_t)s*BB*HH + idx] = hv;
}

// ------------------------- launch -------------------------
extern "C" void kernel_launch(void* const* d_in, const int* in_sizes, int n_in,
                              void* d_out, int out_size){
    const float* enc = (const float*)d_in[0];
    const float* efs = (const float*)d_in[1];
    const int*   tgt = (const int*)  d_in[2];
    const float* Qw  = (const float*)d_in[3];
    const float* Qb  = (const float*)d_in[4];
    const float* Kw  = (const float*)d_in[5];
    const float* Kb  = (const float*)d_in[6];
    const float* Vw  = (const float*)d_in[7];
    const float* Vb  = (const float*)d_in[8];
    const float* emb = (const float*)d_in[9];
    const float* Wih0= (const float*)d_in[10];
    const float* Whh0= (const float*)d_in[11];
    const float* bih0= (const float*)d_in[12];
    const float* bhh0= (const float*)d_in[13];
    const float* Wih1= (const float*)d_in[14];
    const float* Whh1= (const float*)d_in[15];
    const float* bih1= (const float*)d_in[16];
    const float* bhh1= (const float*)d_in[17];
    const float* Pw  = (const float*)d_in[18];
    const float* Pb  = (const float*)d_in[19];
    float* out = (float*)d_out;

    float *p_xemb, *p_giEmb, *p_kproj, *p_hstates;
    __nv_bfloat16* p_kprojh;
    cudaGetSymbolAddress((void**)&p_xemb,    d_xemb);
    cudaGetSymbolAddress((void**)&p_giEmb,   d_giEmb);
    cudaGetSymbolAddress((void**)&p_kproj,   d_kproj);
    cudaGetSymbolAddress((void**)&p_kprojh,  d_kprojh);
    cudaGetSymbolAddress((void**)&p_hstates, d_hstates);

    // one-time precomputation
    k_init<<<(BB*HH + 255)/256, 256>>>(efs);
    k_embed<<<SS*BB, 128>>>(tgt, emb);
    k_enc2bf<<<LTD, 256>>>(enc);
    {   // gi_emb[s,b,:] = relu(emb) @ Wih0[:, :EE]^T + bih0
        dim3 g(SS*BB/128, (3*HH)/64, 1);
        k_sgemm<false><<<g, 256>>>(p_xemb, EE, 0, Wih0, EE+HH, 0, bih0, 0,
                                   p_giEmb, 3*HH, 0, nullptr, SS*BB, 3*HH, EE);
    }
    {   // kproj[l,t,b,:] = enc @ Kw[l]^T + Kb[l]  (+ fused bf16 side-write)
        dim3 g(TT*BB/128, (AT+63)/64, LL);
        k_sgemm<false><<<g, 256>>>(enc, HH, (long long)TT*BB*HH,
                                   Kw, HH, (long long)AT*HH,
                                   Kb, AT,
                                   p_kproj, AT, (long long)TT*BB*AT,
                                   p_kprojh,
                                   TT*BB, AT, HH);
    }

    // sequential decode loop: 7 nodes per step
    for (int s = 0; s < SS; s++){
        int cur = s & 1;
        k_front<<<242, 256>>>(Qw, Qb, Whh0, Whh1, cur);
        { dim3 gs(LTD/64, BB); k_scores<<<gs, 256>>>(Vw, Vb); }
        { dim3 gc(BB, 4); k_ctx<<<gc, 256>>>(); }
        k_gru1<<<96, 256>>>(0, cur, Wih0, Wih1);
        k_gates0<<<BB*HH/256, 256>>>(cur, s, bhh0);
        k_gru1<<<96, 256>>>(2, cur, Wih0, Wih1);
        k_gates1<<<BB*HH/256, 256>>>(cur, s, bih1, bhh1);
    }

    {   // deferred output projection: logits = hstates @ Pw^T + Pb, permuted to (B,S,V)
        dim3 g(SS*BB/128, (VV+63)/64, 1);
        k_sgemm<true><<<g, 256>>>(p_hstates, HH, 0, Pw, HH, 0, Pb, 0,
                                  out, VV, 0, nullptr, SS*BB, VV, HH);
    }
}

// round 15
// speedup vs baseline: 1.3404x; 1.0776x over previous
#include <cuda_runtime.h>
#include <cuda_bf16.h>
#include <math.h>
#include <string.h>

#define LL 2
#define TT 512
#define BB 64
#define HH 512
#define AT 200
#define EE 512
#define VV 10000
#define SS 128
#define LTD (LL*TT)   // 1024

// ------------------------- scratch (static device memory) -------------------------
__device__ __nv_bfloat16 d_kprojh[(size_t)LL*TT*BB*AT];   // bf16 kproj (26 MB)
__device__ __nv_bfloat16 d_ench[(size_t)BB*LTD*HH];       // enc transposed (b,lt,h) bf16 (67 MB)
__device__ float d_xemb [(size_t)SS*BB*EE];
__device__ float d_giEmb[(size_t)SS*BB*3*HH];
__device__ float d_hstates[(size_t)SS*BB*HH];
__device__ float d_h0[2][BB*HH];
__device__ float d_h1[2][BB*HH];
__device__ float d_q[LL*BB*AT];
__device__ float d_scores[BB*LTD];
__device__ float d_ctxp[4*BB*HH];                         // 4 lt-split partial contexts
__device__ float d_gh0[BB*3*HH];
__device__ float d_gh1[BB*3*HH];

__device__ __forceinline__ float sigm(float x){ return 1.0f/(1.0f + __expf(-x)); }
__device__ __forceinline__ float tanh_fast(float x){
    float y; asm("tanh.approx.f32 %0, %1;" : "=f"(y) : "f"(x)); return y;
}

__device__ __forceinline__ float2 ffma2(float2 a, float2 b, float2 c){
    unsigned long long ua, ub, uc, ud;
    memcpy(&ua, &a, 8); memcpy(&ub, &b, 8); memcpy(&uc, &c, 8);
    asm("fma.rn.f32x2 %0, %1, %2, %3;" : "=l"(ud) : "l"(ua), "l"(ub), "l"(uc));
    float2 d; memcpy(&d, &ud, 8);
    return d;
}

// ------------------------- init h from encoder_final_states -------------------------
__global__ void k_init(const float* __restrict__ efs){
    int i = blockIdx.x*blockDim.x + threadIdx.x;
    if (i < BB*HH){ d_h0[0][i] = efs[i]; d_h1[0][i] = efs[BB*HH + i]; }
}

// ------------------------- embedding + relu for all steps -------------------------
__global__ void k_embed(const int* __restrict__ tgt, const float* __restrict__ emb){
    int sb = blockIdx.x;           // s*BB + b
    int s = sb / BB, b = sb % BB;
    int tok = (s == 0) ? 0 : tgt[b*SS + (s-1)];
    const float4* src = reinterpret_cast<const float4*>(emb + (size_t)tok*EE);
    float4* dst = reinterpret_cast<float4*>(d_xemb + (size_t)sb*EE);
    float4 v = src[threadIdx.x];
    v.x = fmaxf(v.x, 0.f); v.y = fmaxf(v.y, 0.f); v.z = fmaxf(v.z, 0.f); v.w = fmaxf(v.w, 0.f);
    dst[threadIdx.x] = v;
}

// ------------------------- enc bf16 transpose (once) -------------------------
__global__ void k_enc2bf(const float* __restrict__ enc){
    int lt = blockIdx.x;   // 1024
    int tid = threadIdx.x; // 256
    for (int b = 0; b < BB; b++){
        float2 v = *reinterpret_cast<const float2*>(enc + ((size_t)lt*BB + b)*HH + 2*tid);
        reinterpret_cast<__nv_bfloat162*>(d_ench + ((size_t)b*LTD + lt)*HH)[tid] =
            __floats2bfloat162_rn(v.x, v.y);
    }
}

// ------------------------- generic fp32 NT-GEMM (fp32 and/or bf16 outputs) ------------------
template<bool PERM>
__global__ void __launch_bounds__(256) k_sgemm(
    const float* __restrict__ Ag, int lda, long long strideA,
    const float* __restrict__ Bg, int ldb, long long strideB,
    const float* __restrict__ bias, int strideBias,
    float* __restrict__ Cg, int ldc, long long strideC,
    __nv_bfloat16* __restrict__ Chg,
    int M, int N, int K)
{
    int z = blockIdx.z;
    const float* A  = Ag + (size_t)z*strideA;
    const float* Bw = Bg + (size_t)z*strideB;
    float* C = Cg ? (Cg + (size_t)z*strideC) : nullptr;
    __nv_bfloat16* Ch = Chg ? (Chg + (size_t)z*strideC) : nullptr;
    const float* bi = bias ? (bias + (size_t)z*strideBias) : nullptr;

    __shared__ float As[16][132];
    __shared__ float Bs[16][68];

    int m0 = blockIdx.x*128, n0 = blockIdx.y*64;
    int tid = threadIdx.x;
    int ty = tid >> 4, tx = tid & 15;

    float2 acc2[4][4];
    #pragma unroll
    for (int i=0;i<4;i++)
        #pragma unroll
        for (int j=0;j<4;j++) acc2[i][j] = make_float2(0.f, 0.f);

    for (int k0 = 0; k0 < K; k0 += 16){
        #pragma unroll
        for (int r=0;r<2;r++){
            int id = tid + r*256;
            int row = id >> 2, kc = (id & 3) << 2;
            float4 v = *reinterpret_cast<const float4*>(A + (size_t)(m0+row)*lda + k0 + kc);
            As[kc+0][row]=v.x; As[kc+1][row]=v.y; As[kc+2][row]=v.z; As[kc+3][row]=v.w;
        }
        {
            int row = tid >> 2, kc = (tid & 3) << 2;
            float4 v = make_float4(0.f,0.f,0.f,0.f);
            if (n0 + row < N)
                v = *reinterpret_cast<const float4*>(Bw + (size_t)(n0+row)*ldb + k0 + kc);
            Bs[kc+0][row]=v.x; Bs[kc+1][row]=v.y; Bs[kc+2][row]=v.z; Bs[kc+3][row]=v.w;
        }
        __syncthreads();
        #pragma unroll
        for (int kk=0; kk<16; kk++){
            const float2* ap2 = reinterpret_cast<const float2*>(&As[kk][ty*8]);
            float2 ap[4] = {ap2[0], ap2[1], ap2[2], ap2[3]};
            float4 b4 = *reinterpret_cast<const float4*>(&Bs[kk][tx*4]);
            float2 bd[4] = {make_float2(b4.x,b4.x), make_float2(b4.y,b4.y),
                            make_float2(b4.z,b4.z), make_float2(b4.w,b4.w)};
            #pragma unroll
            for (int i=0;i<4;i++)
                #pragma unroll
                for (int j=0;j<4;j++)
                    acc2[i][j] = ffma2(ap[i], bd[j], acc2[i][j]);
        }
        __syncthreads();
    }

    #pragma unroll
    for (int i=0;i<4;i++){
        #pragma unroll
        for (int j=0;j<4;j++){
            int n = n0 + tx*4 + j;
            if (n < N){
                float add = bi ? bi[n] : 0.f;
                float vx = acc2[i][j].x + add;
                float vy = acc2[i][j].y + add;
                int mx = m0 + ty*8 + i*2;
                if (PERM){
                    int srow = mx >> 6, brow = mx & 63;
                    C[((size_t)brow*SS + srow)*VV + n] = vx;
                    int my = mx + 1;
                    srow = my >> 6; brow = my & 63;
                    C[((size_t)brow*SS + srow)*VV + n] = vy;
                } else {
                    if (C){
                        C[(size_t)mx*ldc + n] = vx;
                        C[(size_t)(mx+1)*ldc + n] = vy;
                    }
                    if (Ch){
                        Ch[(size_t)mx*ldc + n] = __float2bfloat16(vx);
                        Ch[(size_t)(mx+1)*ldc + n] = __float2bfloat16(vy);
                    }
                }
            }
        }
    }
}

// =================== step node 1: front = gh0 (96) + gh1 (96) + coalesced-tiled q (32) =========
__global__ void __launch_bounds__(256) k_front(
    const float* __restrict__ Qw, const float* __restrict__ Qb,
    const float* __restrict__ Whh0, const float* __restrict__ Whh1, int cur)
{
    __shared__ float sbuf[2048];   // 8KB: gh aliases As/Bs; q uses hs[4][512]
    int bid = blockIdx.x, tid = threadIdx.x;

    if (bid < 192){
        // ---- gh role (validated body): gh = h @ Whh^T ----
        int mode1 = bid >= 96;               // 0: gh0, 1: gh1
        int n0 = (bid % 96) * 16;
        const float* Aa = mode1 ? d_h1[cur] : d_h0[cur];
        const float* Bw = mode1 ? Whh1 : Whh0;
        float* C = mode1 ? d_gh1 : d_gh0;

        float (*As)[68] = reinterpret_cast<float(*)[68]>(sbuf);
        float (*Bs)[20] = reinterpret_cast<float(*)[20]>(sbuf + 16*68);
        int ty = tid >> 4, tx = tid & 15;
        int tm0 = ty*4;
        int arow = tid >> 2, akc = (tid & 3) << 2;
        float acc0=0.f, acc1=0.f, acc2=0.f, acc3=0.f;

        for (int k0=0; k0<HH; k0+=16){
            float4 av = *reinterpret_cast<const float4*>(Aa + (size_t)arow*HH + k0 + akc);
            As[akc+0][arow]=av.x; As[akc+1][arow]=av.y; As[akc+2][arow]=av.z; As[akc+3][arow]=av.w;
            if (tid < 64){
                float4 bv = *reinterpret_cast<const float4*>(Bw + (size_t)(n0 + arow)*HH + k0 + akc);
                Bs[akc+0][arow]=bv.x; Bs[akc+1][arow]=bv.y; Bs[akc+2][arow]=bv.z; Bs[akc+3][arow]=bv.w;
            }
            __syncthreads();
            #pragma unroll
            for (int kk=0; kk<16; kk++){
                float4 a = *reinterpret_cast<const float4*>(&As[kk][tm0]);
                float bv = Bs[kk][tx];
                acc0 = fmaf(a.x, bv, acc0);
                acc1 = fmaf(a.y, bv, acc1);
                acc2 = fmaf(a.z, bv, acc2);
                acc3 = fmaf(a.w, bv, acc3);
            }
            __syncthreads();
        }
        int n = n0 + tx;
        C[(size_t)(tm0+0)*(3*HH) + n] = acc0;
        C[(size_t)(tm0+1)*(3*HH) + n] = acc1;
        C[(size_t)(tm0+2)*(3*HH) + n] = acc2;
        C[(size_t)(tm0+3)*(3*HH) + n] = acc3;
        return;
    }

    // ---- q role: block owns (l, 4 b's); h rows staged in smem (coalesced); Qw streamed coalesced ----
    {
        int r = bid - 192;                   // 0..31
        int l = r >> 4;                      // 0..1
        int b0 = (r & 15) * 4;
        const float* hsrc = l ? d_h1[cur] : d_h0[cur];
        // load 4 h rows (coalesced: consecutive tids -> consecutive columns)
        for (int i = tid; i < 4*HH; i += 256)
            sbuf[i] = hsrc[(size_t)(b0 + (i >> 9))*HH + (i & 511)];
        __syncthreads();

        int w = tid >> 5, lane = tid & 31;
        for (int a = w; a < AT; a += 8){
            const float4* wr = reinterpret_cast<const float4*>(Qw + (size_t)(l*AT + a)*HH);
            float acc[4] = {0.f, 0.f, 0.f, 0.f};
            #pragma unroll
            for (int kq = 0; kq < 4; kq++){
                int k = lane + kq*32;
                float4 q4 = wr[k];
                #pragma unroll
                for (int r4=0;r4<4;r4++){
                    float4 h4 = *reinterpret_cast<const float4*>(&sbuf[r4*HH + k*4]);
                    acc[r4] += q4.x*h4.x + q4.y*h4.y + q4.z*h4.z + q4.w*h4.w;
                }
            }
            float qb = Qb[l*AT + a];
            #pragma unroll
            for (int r4=0;r4<4;r4++){
                float s = acc[r4];
                #pragma unroll
                for (int off=16; off; off>>=1) s += __shfl_xor_sync(0xffffffffu, s, off);
                if (lane == 0) d_q[(size_t)(l*BB + b0 + r4)*AT + a] = s + qb;
            }
        }
    }
}

// ------------------------- scores from bf16 kproj (validated R7 body) -------------------------
__global__ void __launch_bounds__(256) k_scores(const float* __restrict__ Vw, const float* __restrict__ Vb){
    int b = blockIdx.y;
    int lt0 = blockIdx.x*64;
    int l = lt0 >> 9;
    int w = threadIdx.x >> 5, lane = threadIdx.x & 31;

    float q8[8], v8[8];
    if (lane < 25){
        const float4* qp = reinterpret_cast<const float4*>(d_q + (size_t)(l*BB + b)*AT + lane*8);
        const float4* vp = reinterpret_cast<const float4*>(Vw + l*AT + lane*8);
        float4 a = qp[0], c = qp[1], e = vp[0], f = vp[1];
        q8[0]=a.x;q8[1]=a.y;q8[2]=a.z;q8[3]=a.w;q8[4]=c.x;q8[5]=c.y;q8[6]=c.z;q8[7]=c.w;
        v8[0]=e.x;v8[1]=e.y;v8[2]=e.z;v8[3]=e.w;v8[4]=f.x;v8[5]=f.y;v8[6]=f.z;v8[7]=f.w;
    } else {
        #pragma unroll
        for (int i=0;i<8;i++){ q8[i]=0.f; v8[i]=0.f; }
    }
    float vb = Vb[l];

    const uint4* kp = reinterpret_cast<const uint4*>(d_kprojh);
    int lt = lt0 + w*8;
    size_t row = ((size_t)lt*BB + b)*25;
    uint4 cur = make_uint4(0,0,0,0);
    if (lane < 25) cur = kp[row + lane];

    #pragma unroll
    for (int r=0;r<8;r++){
        uint4 nxt = make_uint4(0,0,0,0);
        if (r < 7 && lane < 25) nxt = kp[row + (size_t)(r+1)*BB*25 + lane];
        const __nv_bfloat162* p = reinterpret_cast<const __nv_bfloat162*>(&cur);
        float sum = 0.f;
        #pragma unroll
        for (int j=0;j<4;j++){
            float2 f2 = __bfloat1622float2(p[j]);
            sum = fmaf(v8[2*j+0], tanh_fast(f2.x + q8[2*j+0]), sum);
            sum = fmaf(v8[2*j+1], tanh_fast(f2.y + q8[2*j+1]), sum);
        }
        #pragma unroll
        for (int off=16; off; off>>=1) sum += __shfl_xor_sync(0xffffffffu, sum, off);
        if (lane == 0) d_scores[(size_t)b*LTD + lt + r] = sum + vb;
        cur = nxt;
    }
}

// ------------------------- fused softmax + partial context (validated R7 body) -----------------
__global__ void __launch_bounds__(256) k_ctx(){
    __shared__ float sw[LTD];
    __shared__ float red[256];
    int b = blockIdx.x, c = blockIdx.y, tid = threadIdx.x;

    float4 s4 = *reinterpret_cast<const float4*>(d_scores + (size_t)b*LTD + tid*4);
    float mx = fmaxf(fmaxf(s4.x, s4.y), fmaxf(s4.z, s4.w));
    red[tid] = mx; __syncthreads();
    for (int st=128; st>0; st>>=1){ if (tid<st) red[tid]=fmaxf(red[tid],red[tid+st]); __syncthreads(); }
    float m = red[0]; __syncthreads();
    float e0 = __expf(s4.x-m), e1 = __expf(s4.y-m), e2 = __expf(s4.z-m), e3 = __expf(s4.w-m);
    sw[tid*4+0]=e0; sw[tid*4+1]=e1; sw[tid*4+2]=e2; sw[tid*4+3]=e3;
    red[tid] = e0+e1+e2+e3; __syncthreads();
    for (int st=128; st>0; st>>=1){ if (tid<st) red[tid]+=red[tid+st]; __syncthreads(); }
    float inv = 1.0f/red[0]; __syncthreads();
    sw[c*256 + tid] *= inv;
    __syncthreads();

    const __nv_bfloat162* ep = reinterpret_cast<const __nv_bfloat162*>(d_ench) +
                               ((size_t)b*LTD + c*256)*(HH/2) + tid;
    const float* wc = &sw[c*256];
    float ax = 0.f, ay = 0.f;
    #pragma unroll 16
    for (int j=0;j<256;j++){
        float wj = wc[j];
        float2 f2 = __bfloat1622float2(ep[(size_t)j*(HH/2)]);
        ax = fmaf(wj, f2.x, ax);
        ay = fmaf(wj, f2.y, ay);
    }
    float2* outp = reinterpret_cast<float2*>(d_ctxp + (size_t)c*BB*HH + (size_t)b*HH) + tid;
    *outp = make_float2(ax, ay);
}

// =================== step nodes 4/5: gi GEMM (gate-major j-tile) + fused gates ===================
// 128 blocks, 256 threads. Block owns j-tile of 4; loads B rows {g*HH + j0+jj} so each
// thread (b=tid>>2, j=j0+(tid&3)) accumulates all 3 gates and applies the GRU update.
__global__ void __launch_bounds__(256) k_layer(
    int layer, int cur, int s,
    const float* __restrict__ Wih0, const float* __restrict__ Wih1,
    const float* __restrict__ bih1,
    const float* __restrict__ bhh0, const float* __restrict__ bhh1)
{
    __shared__ float As[16][68];
    __shared__ float Bs[16][16];
    int tid = threadIdx.x;
    int j0 = blockIdx.x*4;

    const float* Bw = layer ? Wih1 : (Wih0 + EE);
    int ldb         = layer ? HH : (EE + HH);

    int arow = tid >> 2, akc = (tid & 3) << 2;
    float accr = 0.f, accz = 0.f, accn = 0.f;

    for (int k0 = 0; k0 < HH; k0 += 16){
        // A tile: layer0 = merged ctx partials; layer1 = h0new
        float4 av;
        if (layer == 0){
            const float* p = d_ctxp + (size_t)arow*HH + k0 + akc;
            float4 a0 = *reinterpret_cast<const float4*>(p);
            float4 a1 = *reinterpret_cast<const float4*>(p + BB*HH);
            float4 a2 = *reinterpret_cast<const float4*>(p + 2*BB*HH);
            float4 a3 = *reinterpret_cast<const float4*>(p + 3*BB*HH);
            av.x = a0.x+a1.x+a2.x+a3.x; av.y = a0.y+a1.y+a2.y+a3.y;
            av.z = a0.z+a1.z+a2.z+a3.z; av.w = a0.w+a1.w+a2.w+a3.w;
        } else {
            av = *reinterpret_cast<const float4*>(d_h0[cur^1] + (size_t)arow*HH + k0 + akc);
        }
        As[akc+0][arow]=av.x; As[akc+1][arow]=av.y; As[akc+2][arow]=av.z; As[akc+3][arow]=av.w;
        // B tile: 12 rows (3 gates x 4 j)
        if (tid < 48){
            int brow = tid >> 2, bkc = (tid & 3) << 2;
            int g = brow >> 2, jj2 = brow & 3;
            int grow = g*HH + j0 + jj2;
            float4 bv = *reinterpret_cast<const float4*>(Bw + (size_t)grow*ldb + k0 + bkc);
            Bs[bkc+0][brow]=bv.x; Bs[bkc+1][brow]=bv.y; Bs[bkc+2][brow]=bv.z; Bs[bkc+3][brow]=bv.w;
        }
        __syncthreads();
        int m = tid >> 2, jj = tid & 3;
        #pragma unroll
        for (int kk=0; kk<16; kk++){
            float a = As[kk][m];
            accr = fmaf(a, Bs[kk][jj],     accr);
            accz = fmaf(a, Bs[kk][4+jj],   accz);
            accn = fmaf(a, Bs[kk][8+jj],   accn);
        }
        __syncthreads();
    }

    // fused gates epilogue
    int b = tid >> 2, j = j0 + (tid & 3);
    size_t gb = (size_t)b*3*HH;
    if (layer == 0){
        const float* ge = d_giEmb + (size_t)s*BB*3*HH;
        float gr = accr + ge[gb + j]        + d_gh0[gb + j]        + bhh0[j];
        float gz = accz + ge[gb + HH + j]   + d_gh0[gb + HH + j]   + bhh0[HH + j];
        float gn = accn + ge[gb + 2*HH + j];
        float hn = d_gh0[gb + 2*HH + j] + bhh0[2*HH + j];
        float r = sigm(gr);
        float z = sigm(gz);
        float n = tanhf(gn + r*hn);
        d_h0[cur^1][(size_t)b*HH + j] = (1.0f - z)*n + z*d_h0[cur][(size_t)b*HH + j];
    } else {
        float gr = accr + bih1[j]        + d_gh1[gb + j]        + bhh1[j];
        float gz = accz + bih1[HH + j]   + d_gh1[gb + HH + j]   + bhh1[HH + j];
        float gn = accn + bih1[2*HH + j];
        float hn = d_gh1[gb + 2*HH + j] + bhh1[2*HH + j];
        float r = sigm(gr);
        float z = sigm(gz);
        float n = tanhf(gn + r*hn);
        float hv = (1.0f - z)*n + z*d_h1[cur][(size_t)b*HH + j];
        d_h1[cur^1][(size_t)b*HH + j] = hv;
        d_hstates[(size_t)s*BB*HH + (size_t)b*HH + j] = hv;
    }
}

// ------------------------- launch -------------------------
extern "C" void kernel_launch(void* const* d_in, const int* in_sizes, int n_in,
                              void* d_out, int out_size){
    const float* enc = (const float*)d_in[0];
    const float* efs = (const float*)d_in[1];
    const int*   tgt = (const int*)  d_in[2];
    const float* Qw  = (const float*)d_in[3];
    const float* Qb  = (const float*)d_in[4];
    const float* Kw  = (const float*)d_in[5];
    const float* Kb  = (const float*)d_in[6];
    const float* Vw  = (const float*)d_in[7];
    const float* Vb  = (const float*)d_in[8];
    const float* emb = (const float*)d_in[9];
    const float* Wih0= (const float*)d_in[10];
    const float* Whh0= (const float*)d_in[11];
    const float* bih0= (const float*)d_in[12];
    const float* bhh0= (const float*)d_in[13];
    const float* Wih1= (const float*)d_in[14];
    const float* Whh1= (const float*)d_in[15];
    const float* bih1= (const float*)d_in[16];
    const float* bhh1= (const float*)d_in[17];
    const float* Pw  = (const float*)d_in[18];
    const float* Pb  = (const float*)d_in[19];
    float* out = (float*)d_out;

    float *p_xemb, *p_giEmb, *p_hstates;
    __nv_bfloat16* p_kprojh;
    cudaGetSymbolAddress((void**)&p_xemb,    d_xemb);
    cudaGetSymbolAddress((void**)&p_giEmb,   d_giEmb);
    cudaGetSymbolAddress((void**)&p_kprojh,  d_kprojh);
    cudaGetSymbolAddress((void**)&p_hstates, d_hstates);

    // one-time precomputation
    k_init<<<(BB*HH + 255)/256, 256>>>(efs);
    k_embed<<<SS*BB, 128>>>(tgt, emb);
    k_enc2bf<<<LTD, 256>>>(enc);
    {   // gi_emb[s,b,:] = relu(emb) @ Wih0[:, :EE]^T + bih0
        dim3 g(SS*BB/128, (3*HH)/64, 1);
        k_sgemm<false><<<g, 256>>>(p_xemb, EE, 0, Wih0, EE+HH, 0, bih0, 0,
                                   p_giEmb, 3*HH, 0, nullptr, SS*BB, 3*HH, EE);
    }
    {   // kproj[l,t,b,:] = enc @ Kw[l]^T + Kb[l], bf16 output only
        dim3 g(TT*BB/128, (AT+63)/64, LL);
        k_sgemm<false><<<g, 256>>>(enc, HH, (long long)TT*BB*HH,
                                   Kw, HH, (long long)AT*HH,
                                   Kb, AT,
                                   nullptr, AT, (long long)TT*BB*AT,
                                   p_kprojh,
                                   TT*BB, AT, HH);
    }

    // sequential decode loop: 5 nodes per step
    for (int s = 0; s < SS; s++){
        int cur = s & 1;
        k_front<<<224, 256>>>(Qw, Qb, Whh0, Whh1, cur);
        { dim3 gs(LTD/64, BB); k_scores<<<gs, 256>>>(Vw, Vb); }
        { dim3 gc(BB, 4); k_ctx<<<gc, 256>>>(); }
        k_layer<<<128, 256>>>(0, cur, s, Wih0, Wih1, bih1, bhh0, bhh1);
        k_layer<<<128, 256>>>(1, cur, s, Wih0, Wih1, bih1, bhh0, bhh1);
    }

    {   // deferred output projection: logits = hstates @ Pw^T + Pb, permuted to (B,S,V)
        dim3 g(SS*BB/128, (VV+63)/64, 1);
        k_sgemm<true><<<g, 256>>>(p_hstates, HH, 0, Pw, HH, 0, Pb, 0,
                                  out, VV, 0, nullptr, SS*BB, VV, HH);
    }
}

// round 17
// speedup vs baseline: 1.3779x; 1.0279x over previous
#include <cuda_runtime.h>
#include <cuda_bf16.h>
#include <math.h>
#include <string.h>

#define LL 2
#define TT 512
#define BB 64
#define HH 512
#define AT 200
#define EE 512
#define VV 10000
#define SS 128
#define LTD (LL*TT)   // 1024

// ------------------------- scratch (static device memory) -------------------------
__device__ __nv_bfloat16 d_kprojh[(size_t)LL*TT*BB*AT];   // bf16 kproj (26 MB)
__device__ __nv_bfloat16 d_ench[(size_t)BB*LTD*HH];       // enc transposed (b,lt,h) bf16 (67 MB)
__device__ float d_xemb [(size_t)SS*BB*EE];
__device__ float d_giEmb[(size_t)SS*BB*3*HH];
__device__ float d_hstates[(size_t)SS*BB*HH];             // fp32 h1 states (16 MB)
__device__ float d_h0[2][BB*HH];
__device__ float d_h1[2][BB*HH];
__device__ float d_q[LL*BB*AT];
__device__ float d_scores[BB*LTD];
__device__ float d_ctxp[4*BB*HH];                         // 4 lt-split partial contexts
__device__ float d_gi0[BB*3*HH];
__device__ float d_gh0[BB*3*HH];
__device__ float d_gi1[BB*3*HH];
__device__ float d_gh1[BB*3*HH];

__device__ __forceinline__ float sigm(float x){ return 1.0f/(1.0f + __expf(-x)); }
__device__ __forceinline__ float tanh_fast(float x){
    float y; asm("tanh.approx.f32 %0, %1;" : "=f"(y) : "f"(x)); return y;
}
__device__ __forceinline__ float2 ffma2(float2 a, float2 b, float2 c){
    unsigned long long ua, ub, uc, ud;
    memcpy(&ua, &a, 8); memcpy(&ub, &b, 8); memcpy(&uc, &c, 8);
    asm("fma.rn.f32x2 %0, %1, %2, %3;" : "=l"(ud) : "l"(ua), "l"(ub), "l"(uc));
    float2 d; memcpy(&d, &ud, 8);
    return d;
}
__device__ __forceinline__ unsigned f2tf32(float x){
    unsigned r; asm("cvt.rna.tf32.f32 %0, %1;" : "=r"(r) : "f"(x)); return r;
}

// ------------------------- init h from encoder_final_states -------------------------
__global__ void k_init(const float* __restrict__ efs){
    int i = blockIdx.x*blockDim.x + threadIdx.x;
    if (i < BB*HH){ d_h0[0][i] = efs[i]; d_h1[0][i] = efs[BB*HH + i]; }
}

// ------------------------- embedding + relu for all steps -------------------------
__global__ void k_embed(const int* __restrict__ tgt, const float* __restrict__ emb){
    int sb = blockIdx.x;           // s*BB + b
    int s = sb / BB, b = sb % BB;
    int tok = (s == 0) ? 0 : tgt[b*SS + (s-1)];
    const float4* src = reinterpret_cast<const float4*>(emb + (size_t)tok*EE);
    float4* dst = reinterpret_cast<float4*>(d_xemb + (size_t)sb*EE);
    float4 v = src[threadIdx.x];
    v.x = fmaxf(v.x, 0.f); v.y = fmaxf(v.y, 0.f); v.z = fmaxf(v.z, 0.f); v.w = fmaxf(v.w, 0.f);
    dst[threadIdx.x] = v;
}

// ------------------------- enc bf16 transpose (once) -------------------------
__global__ void k_enc2bf(const float* __restrict__ enc){
    int lt = blockIdx.x;   // 1024
    int tid = threadIdx.x; // 256
    for (int b = 0; b < BB; b++){
        float2 v = *reinterpret_cast<const float2*>(enc + ((size_t)lt*BB + b)*HH + 2*tid);
        reinterpret_cast<__nv_bfloat162*>(d_ench + ((size_t)b*LTD + lt)*HH)[tid] =
            __floats2bfloat162_rn(v.x, v.y);
    }
}

// ------------------------- generic fp32 NT-GEMM (fp32 and/or bf16 outputs) ------------------
__global__ void __launch_bounds__(256) k_sgemm(
    const float* __restrict__ Ag, int lda, long long strideA,
    const float* __restrict__ Bg, int ldb, long long strideB,
    const float* __restrict__ bias, int strideBias,
    float* __restrict__ Cg, int ldc, long long strideC,
    __nv_bfloat16* __restrict__ Chg,
    int M, int N, int K)
{
    int z = blockIdx.z;
    const float* A  = Ag + (size_t)z*strideA;
    const float* Bw = Bg + (size_t)z*strideB;
    float* C = Cg ? (Cg + (size_t)z*strideC) : nullptr;
    __nv_bfloat16* Ch = Chg ? (Chg + (size_t)z*strideC) : nullptr;
    const float* bi = bias ? (bias + (size_t)z*strideBias) : nullptr;

    __shared__ float As[16][132];
    __shared__ float Bs[16][68];

    int m0 = blockIdx.x*128, n0 = blockIdx.y*64;
    int tid = threadIdx.x;
    int ty = tid >> 4, tx = tid & 15;

    float2 acc2[4][4];
    #pragma unroll
    for (int i=0;i<4;i++)
        #pragma unroll
        for (int j=0;j<4;j++) acc2[i][j] = make_float2(0.f, 0.f);

    for (int k0 = 0; k0 < K; k0 += 16){
        #pragma unroll
        for (int r=0;r<2;r++){
            int id = tid + r*256;
            int row = id >> 2, kc = (id & 3) << 2;
            float4 v = *reinterpret_cast<const float4*>(A + (size_t)(m0+row)*lda + k0 + kc);
            As[kc+0][row]=v.x; As[kc+1][row]=v.y; As[kc+2][row]=v.z; As[kc+3][row]=v.w;
        }
        {
            int row = tid >> 2, kc = (tid & 3) << 2;
            float4 v = make_float4(0.f,0.f,0.f,0.f);
            if (n0 + row < N)
                v = *reinterpret_cast<const float4*>(Bw + (size_t)(n0+row)*ldb + k0 + kc);
            Bs[kc+0][row]=v.x; Bs[kc+1][row]=v.y; Bs[kc+2][row]=v.z; Bs[kc+3][row]=v.w;
        }
        __syncthreads();
        #pragma unroll
        for (int kk=0; kk<16; kk++){
            const float2* ap2 = reinterpret_cast<const float2*>(&As[kk][ty*8]);
            float2 ap[4] = {ap2[0], ap2[1], ap2[2], ap2[3]};
            float4 b4 = *reinterpret_cast<const float4*>(&Bs[kk][tx*4]);
            float2 bd[4] = {make_float2(b4.x,b4.x), make_float2(b4.y,b4.y),
                            make_float2(b4.z,b4.z), make_float2(b4.w,b4.w)};
            #pragma unroll
            for (int i=0;i<4;i++)
                #pragma unroll
                for (int j=0;j<4;j++)
                    acc2[i][j] = ffma2(ap[i], bd[j], acc2[i][j]);
        }
        __syncthreads();
    }

    #pragma unroll
    for (int i=0;i<4;i++){
        #pragma unroll
        for (int j=0;j<4;j++){
            int n = n0 + tx*4 + j;
            if (n < N){
                float add = bi ? bi[n] : 0.f;
                float vx = acc2[i][j].x + add;
                float vy = acc2[i][j].y + add;
                int mx = m0 + ty*8 + i*2;
                if (C){
                    C[(size_t)mx*ldc + n] = vx;
                    C[(size_t)(mx+1)*ldc + n] = vy;
                }
                if (Ch){
                    Ch[(size_t)mx*ldc + n] = __float2bfloat16(vx);
                    Ch[(size_t)(mx+1)*ldc + n] = __float2bfloat16(vy);
                }
            }
        }
    }
}

// =================== step node 1: gh0 (blocks 0..95) + gh1 (96..191) + q (192..3391) ===========
__global__ void __launch_bounds__(256) k_front(
    const float* __restrict__ Qw, const float* __restrict__ Qb,
    const float* __restrict__ Whh0, const float* __restrict__ Whh1, int cur)
{
    __shared__ float As[16][68];
    __shared__ float Bs[16][20];
    int bid = blockIdx.x, tid = threadIdx.x;

    if (bid < 192){
        int mode1 = bid >= 96;
        int n0 = (bid % 96) * 16;
        const float* Aa = mode1 ? d_h1[cur] : d_h0[cur];
        const float* Bw = mode1 ? Whh1 : Whh0;
        float* C = mode1 ? d_gh1 : d_gh0;

        int ty = tid >> 4, tx = tid & 15;
        int tm0 = ty*4;
        int arow = tid >> 2, akc = (tid & 3) << 2;
        float acc0=0.f, acc1=0.f, acc2=0.f, acc3=0.f;

        for (int k0=0; k0<HH; k0+=16){
            float4 av = *reinterpret_cast<const float4*>(Aa + (size_t)arow*HH + k0 + akc);
            As[akc+0][arow]=av.x; As[akc+1][arow]=av.y; As[akc+2][arow]=av.z; As[akc+3][arow]=av.w;
            if (tid < 64){
                float4 bv = *reinterpret_cast<const float4*>(Bw + (size_t)(n0 + arow)*HH + k0 + akc);
                Bs[akc+0][arow]=bv.x; Bs[akc+1][arow]=bv.y; Bs[akc+2][arow]=bv.z; Bs[akc+3][arow]=bv.w;
            }
            __syncthreads();
            #pragma unroll
            for (int kk=0; kk<16; kk++){
                float4 a = *reinterpret_cast<const float4*>(&As[kk][tm0]);
                float bv = Bs[kk][tx];
                acc0 = fmaf(a.x, bv, acc0);
                acc1 = fmaf(a.y, bv, acc1);
                acc2 = fmaf(a.z, bv, acc2);
                acc3 = fmaf(a.w, bv, acc3);
            }
            __syncthreads();
        }
        int n = n0 + tx;
        C[(size_t)(tm0+0)*(3*HH) + n] = acc0;
        C[(size_t)(tm0+1)*(3*HH) + n] = acc1;
        C[(size_t)(tm0+2)*(3*HH) + n] = acc2;
        C[(size_t)(tm0+3)*(3*HH) + n] = acc3;
        return;
    }

    // ---- q role (exact R7 k_q body, block index shifted) ----
    {
        int gw = ((bid - 192)*256 + tid) >> 5;
        int lane = tid & 31;
        int l = gw / (BB*AT);
        int rem = gw - l*(BB*AT);
        int b = rem / AT;
        int a = rem - b*AT;
        const float4* hr = reinterpret_cast<const float4*>((l==0 ? d_h0[cur] : d_h1[cur]) + (size_t)b*HH);
        const float4* wr = reinterpret_cast<const float4*>(Qw + (size_t)(l*AT + a)*HH);
        float sum = 0.f;
        #pragma unroll
        for (int i=0;i<4;i++){
            float4 h4 = hr[lane + i*32];
            float4 w4 = wr[lane + i*32];
            sum += h4.x*w4.x + h4.y*w4.y + h4.z*w4.z + h4.w*w4.w;
        }
        #pragma unroll
        for (int off=16; off; off>>=1) sum += __shfl_xor_sync(0xffffffffu, sum, off);
        if (lane == 0) d_q[gw] = sum + Qb[l*AT + a];
    }
}

// ------------------------- scores from bf16 kproj (exact R7 body) -------------------------
__global__ void __launch_bounds__(256) k_scores(const float* __restrict__ Vw, const float* __restrict__ Vb){
    int b = blockIdx.y;
    int lt0 = blockIdx.x*64;
    int l = lt0 >> 9;
    int w = threadIdx.x >> 5, lane = threadIdx.x & 31;

    float q8[8], v8[8];
    if (lane < 25){
        const float4* qp = reinterpret_cast<const float4*>(d_q + (size_t)(l*BB + b)*AT + lane*8);
        const float4* vp = reinterpret_cast<const float4*>(Vw + l*AT + lane*8);
        float4 a = qp[0], c = qp[1], e = vp[0], f = vp[1];
        q8[0]=a.x;q8[1]=a.y;q8[2]=a.z;q8[3]=a.w;q8[4]=c.x;q8[5]=c.y;q8[6]=c.z;q8[7]=c.w;
        v8[0]=e.x;v8[1]=e.y;v8[2]=e.z;v8[3]=e.w;v8[4]=f.x;v8[5]=f.y;v8[6]=f.z;v8[7]=f.w;
    } else {
        #pragma unroll
        for (int i=0;i<8;i++){ q8[i]=0.f; v8[i]=0.f; }
    }
    float vb = Vb[l];

    const uint4* kp = reinterpret_cast<const uint4*>(d_kprojh);
    int lt = lt0 + w*8;
    size_t row = ((size_t)lt*BB + b)*25;
    uint4 cur = make_uint4(0,0,0,0);
    if (lane < 25) cur = kp[row + lane];

    #pragma unroll
    for (int r=0;r<8;r++){
        uint4 nxt = make_uint4(0,0,0,0);
        if (r < 7 && lane < 25) nxt = kp[row + (size_t)(r+1)*BB*25 + lane];
        const __nv_bfloat162* p = reinterpret_cast<const __nv_bfloat162*>(&cur);
        float sum = 0.f;
        #pragma unroll
        for (int j=0;j<4;j++){
            float2 f2 = __bfloat1622float2(p[j]);
            sum = fmaf(v8[2*j+0], tanh_fast(f2.x + q8[2*j+0]), sum);
            sum = fmaf(v8[2*j+1], tanh_fast(f2.y + q8[2*j+1]), sum);
        }
        #pragma unroll
        for (int off=16; off; off>>=1) sum += __shfl_xor_sync(0xffffffffu, sum, off);
        if (lane == 0) d_scores[(size_t)b*LTD + lt + r] = sum + vb;
        cur = nxt;
    }
}

// ------------------------- fused softmax + partial context (exact R7 body) -----------------
__global__ void __launch_bounds__(256) k_ctx(){
    __shared__ float sw[LTD];
    __shared__ float red[256];
    int b = blockIdx.x, c = blockIdx.y, tid = threadIdx.x;

    float4 s4 = *reinterpret_cast<const float4*>(d_scores + (size_t)b*LTD + tid*4);
    float mx = fmaxf(fmaxf(s4.x, s4.y), fmaxf(s4.z, s4.w));
    red[tid] = mx; __syncthreads();
    for (int st=128; st>0; st>>=1){ if (tid<st) red[tid]=fmaxf(red[tid],red[tid+st]); __syncthreads(); }
    float m = red[0]; __syncthreads();
    float e0 = __expf(s4.x-m), e1 = __expf(s4.y-m), e2 = __expf(s4.z-m), e3 = __expf(s4.w-m);
    sw[tid*4+0]=e0; sw[tid*4+1]=e1; sw[tid*4+2]=e2; sw[tid*4+3]=e3;
    red[tid] = e0+e1+e2+e3; __syncthreads();
    for (int st=128; st>0; st>>=1){ if (tid<st) red[tid]+=red[tid+st]; __syncthreads(); }
    float inv = 1.0f/red[0]; __syncthreads();
    sw[c*256 + tid] *= inv;
    __syncthreads();

    const __nv_bfloat162* ep = reinterpret_cast<const __nv_bfloat162*>(d_ench) +
                               ((size_t)b*LTD + c*256)*(HH/2) + tid;
    const float* wc = &sw[c*256];
    float ax = 0.f, ay = 0.f;
    #pragma unroll 16
    for (int j=0;j<256;j++){
        float wj = wc[j];
        float2 f2 = __bfloat1622float2(ep[(size_t)j*(HH/2)]);
        ax = fmaf(wj, f2.x, ax);
        ay = fmaf(wj, f2.y, ay);
    }
    float2* outp = reinterpret_cast<float2*>(d_ctxp + (size_t)c*BB*HH + (size_t)b*HH) + tid;
    *outp = make_float2(ax, ay);
}

// ------------------------- gi GEMM (exact R11 body; modes 0: gi0 ctx-merge, 2: gi1) ----------
__global__ void __launch_bounds__(256) k_gru1(
    int mode, int cur,
    const float* __restrict__ Wih0, const float* __restrict__ Wih1)
{
    const float* Aa = nullptr; const float* Bw; int ldb; float* C;
    bool merge = false;
    if (mode == 0){ merge = true;      Bw = Wih0 + EE; ldb = EE + HH; C = d_gi0; }
    else          { Aa = d_h0[cur^1];  Bw = Wih1;      ldb = HH;      C = d_gi1; }

    __shared__ float As[16][68];
    __shared__ float Bs[16][20];
    int tid = threadIdx.x;
    int n0 = blockIdx.x*16;
    int ty = tid >> 4, tx = tid & 15;
    int tm0 = ty*4;
    int arow = tid >> 2, akc = (tid & 3) << 2;
    float acc0=0.f, acc1=0.f, acc2=0.f, acc3=0.f;

    for (int k0=0; k0<HH; k0+=16){
        float4 av;
        if (merge){
            const float* p = d_ctxp + (size_t)arow*HH + k0 + akc;
            float4 a0 = *reinterpret_cast<const float4*>(p);
            float4 a1 = *reinterpret_cast<const float4*>(p + BB*HH);
            float4 a2 = *reinterpret_cast<const float4*>(p + 2*BB*HH);
            float4 a3 = *reinterpret_cast<const float4*>(p + 3*BB*HH);
            av.x = a0.x+a1.x+a2.x+a3.x; av.y = a0.y+a1.y+a2.y+a3.y;
            av.z = a0.z+a1.z+a2.z+a3.z; av.w = a0.w+a1.w+a2.w+a3.w;
        } else {
            av = *reinterpret_cast<const float4*>(Aa + (size_t)arow*HH + k0 + akc);
        }
        As[akc+0][arow]=av.x; As[akc+1][arow]=av.y; As[akc+2][arow]=av.z; As[akc+3][arow]=av.w;
        if (tid < 64){
            float4 bv = *reinterpret_cast<const float4*>(Bw + (size_t)(n0 + arow)*ldb + k0 + akc);
            Bs[akc+0][arow]=bv.x; Bs[akc+1][arow]=bv.y; Bs[akc+2][arow]=bv.z; Bs[akc+3][arow]=bv.w;
        }
        __syncthreads();
        #pragma unroll
        for (int kk=0; kk<16; kk++){
            float4 a = *reinterpret_cast<const float4*>(&As[kk][tm0]);
            float bv = Bs[kk][tx];
            acc0 = fmaf(a.x, bv, acc0);
            acc1 = fmaf(a.y, bv, acc1);
            acc2 = fmaf(a.z, bv, acc2);
            acc3 = fmaf(a.w, bv, acc3);
        }
        __syncthreads();
    }
    int n = n0 + tx;
    C[(size_t)(tm0+0)*(3*HH) + n] = acc0;
    C[(size_t)(tm0+1)*(3*HH) + n] = acc1;
    C[(size_t)(tm0+2)*(3*HH) + n] = acc2;
    C[(size_t)(tm0+3)*(3*HH) + n] = acc3;
}

// ------------------------- GRU gates (R11 bodies) -------------------------
__global__ void k_gates0(int cur, int s, const float* __restrict__ bhh0){
    int idx = blockIdx.x*256 + threadIdx.x;       // BB*HH
    int b = idx >> 9, j = idx & 511;
    const float* gi = d_gi0 + (size_t)b*3*HH;
    const float* gh = d_gh0 + (size_t)b*3*HH;
    const float* ge = d_giEmb + (size_t)s*BB*3*HH + (size_t)b*3*HH;
    float r = sigm(gi[j] + ge[j] + gh[j] + bhh0[j]);
    float z = sigm(gi[j+HH] + ge[j+HH] + gh[j+HH] + bhh0[j+HH]);
    float n = tanhf(gi[j+2*HH] + ge[j+2*HH] + r*(gh[j+2*HH] + bhh0[j+2*HH]));
    d_h0[cur^1][idx] = (1.0f - z)*n + z*d_h0[cur][idx];
}
__global__ void k_gates1(int cur, int s, const float* __restrict__ bih1, const float* __restrict__ bhh1){
    int idx = blockIdx.x*256 + threadIdx.x;
    int b = idx >> 9, j = idx & 511;
    const float* gi = d_gi1 + (size_t)b*3*HH;
    const float* gh = d_gh1 + (size_t)b*3*HH;
    float r = sigm(gi[j] + bih1[j] + gh[j] + bhh1[j]);
    float z = sigm(gi[j+HH] + bih1[j+HH] + gh[j+HH] + bhh1[j+HH]);
    float n = tanhf(gi[j+2*HH] + bih1[j+2*HH] + r*(gh[j+2*HH] + bhh1[j+2*HH]));
    float hv = (1.0f - z)*n + z*d_h1[cur][idx];
    d_h1[cur^1][idx] = hv;
    d_hstates[(size_t)s*BB*HH + idx] = hv;
}

// =================== tf32 tensor-core projection: out(B,S,V) = H @ Pw^T + Pb ===================
// Block tile 128x64, k-chunk 32. 8 warps as (wm 0..1)x(wn 0..3); warp tile 64x16.
// fp32 operands staged in smem; fragments gathered per-thread and converted to tf32.
#define PKC 32
__global__ void __launch_bounds__(256) k_proj(
    const float* __restrict__ Pw, const float* __restrict__ Pb, float* __restrict__ out)
{
    __shared__ float Af[128][PKC+4];   // stride 36 floats = 144B
    __shared__ float Bf[64][PKC+4];

    int m0 = blockIdx.x*128, n0 = blockIdx.y*64;
    int tid = threadIdx.x, lane = tid & 31, wid = tid >> 5;
    int wm = wid & 1, wn = wid >> 1;

    float d[4][2][4];
    #pragma unroll
    for (int i=0;i<4;i++)
        #pragma unroll
        for (int j=0;j<2;j++)
            #pragma unroll
            for (int r=0;r<4;r++) d[i][j][r] = 0.f;

    int fr = lane >> 2, fc = lane & 3;   // fragment row/col within 8x4

    for (int k0 = 0; k0 < HH; k0 += PKC){
        // stage A: 128 rows x 32 floats
        #pragma unroll
        for (int i=0;i<4;i++){
            int c = tid + i*256;
            int row = c >> 3, cc = (c & 7) << 2;
            *reinterpret_cast<float4*>(&Af[row][cc]) =
                *reinterpret_cast<const float4*>(&d_hstates[(size_t)(m0+row)*HH + k0 + cc]);
        }
        // stage B: 64 rows x 32 floats (guard rows >= VV)
        #pragma unroll
        for (int i=0;i<2;i++){
            int c = tid + i*256;
            int row = c >> 3, cc = (c & 7) << 2;
            float4 v = make_float4(0.f,0.f,0.f,0.f);
            int gr = n0 + row;
            if (gr < VV)
                v = *reinterpret_cast<const float4*>(&Pw[(size_t)gr*HH + k0 + cc]);
            *reinterpret_cast<float4*>(&Bf[row][cc]) = v;
        }
        __syncthreads();

        #pragma unroll
        for (int ks = 0; ks < PKC/8; ks++){
            int k = ks*8;
            unsigned a[4][4], bb[2][2];
            #pragma unroll
            for (int mt=0; mt<4; mt++){
                int rm = wm*64 + mt*16;
                a[mt][0] = f2tf32(Af[rm + fr    ][k + fc    ]);
                a[mt][1] = f2tf32(Af[rm + fr + 8][k + fc    ]);
                a[mt][2] = f2tf32(Af[rm + fr    ][k + fc + 4]);
                a[mt][3] = f2tf32(Af[rm + fr + 8][k + fc + 4]);
            }
            #pragma unroll
            for (int nt=0; nt<2; nt++){
                int nb = wn*16 + nt*8;
                bb[nt][0] = f2tf32(Bf[nb + fr][k + fc    ]);
                bb[nt][1] = f2tf32(Bf[nb + fr][k + fc + 4]);
            }
            #pragma unroll
            for (int mt=0; mt<4; mt++)
                #pragma unroll
                for (int nt=0; nt<2; nt++){
                    asm volatile(
                        "mma.sync.aligned.m16n8k8.row.col.f32.tf32.tf32.f32 "
                        "{%0,%1,%2,%3}, {%4,%5,%6,%7}, {%8,%9}, {%0,%1,%2,%3};"
                        : "+f"(d[mt][nt][0]), "+f"(d[mt][nt][1]), "+f"(d[mt][nt][2]), "+f"(d[mt][nt][3])
                        : "r"(a[mt][0]), "r"(a[mt][1]), "r"(a[mt][2]), "r"(a[mt][3]),
                          "r"(bb[nt][0]), "r"(bb[nt][1]));
                }
        }
        __syncthreads();
    }

    // epilogue: D m16n8 layout — lane l: {d0,d1}=row l/4 cols 2(l%4),+1; {d2,d3}=row l/4+8
    #pragma unroll
    for (int mt=0; mt<4; mt++){
        #pragma unroll
        for (int nt=0; nt<2; nt++){
            int ncol = n0 + wn*16 + nt*8 + ((lane & 3) << 1);
            if (ncol < VV){
                float pb0 = Pb[ncol], pb1 = Pb[ncol+1];
                int mr = m0 + wm*64 + mt*16 + (lane >> 2);
                {   // m = s*BB + b -> out[(b*SS + s)*VV + n]
                    int s = mr >> 6, b = mr & 63;
                    float2* o = reinterpret_cast<float2*>(&out[((size_t)b*SS + s)*VV + ncol]);
                    *o = make_float2(d[mt][nt][0] + pb0, d[mt][nt][1] + pb1);
                }
                {
                    int mr2 = mr + 8;
                    int s = mr2 >> 6, b = mr2 & 63;
                    float2* o = reinterpret_cast<float2*>(&out[((size_t)b*SS + s)*VV + ncol]);
                    *o = make_float2(d[mt][nt][2] + pb0, d[mt][nt][3] + pb1);
                }
            }
        }
    }
}

// ------------------------- launch -------------------------
extern "C" void kernel_launch(void* const* d_in, const int* in_sizes, int n_in,
                              void* d_out, int out_size){
    const float* enc = (const float*)d_in[0];
    const float* efs = (const float*)d_in[1];
    const int*   tgt = (const int*)  d_in[2];
    const float* Qw  = (const float*)d_in[3];
    const float* Qb  = (const float*)d_in[4];
    const float* Kw  = (const float*)d_in[5];
    const float* Kb  = (const float*)d_in[6];
    const float* Vw  = (const float*)d_in[7];
    const float* Vb  = (const float*)d_in[8];
    const float* emb = (const float*)d_in[9];
    const float* Wih0= (const float*)d_in[10];
    const float* Whh0= (const float*)d_in[11];
    const float* bih0= (const float*)d_in[12];
    const float* bhh0= (const float*)d_in[13];
    const float* Wih1= (const float*)d_in[14];
    const float* Whh1= (const float*)d_in[15];
    const float* bih1= (const float*)d_in[16];
    const float* bhh1= (const float*)d_in[17];
    const float* Pw  = (const float*)d_in[18];
    const float* Pb  = (const float*)d_in[19];
    float* out = (float*)d_out;

    float *p_xemb, *p_giEmb;
    __nv_bfloat16* p_kprojh;
    cudaGetSymbolAddress((void**)&p_xemb,   d_xemb);
    cudaGetSymbolAddress((void**)&p_giEmb,  d_giEmb);
    cudaGetSymbolAddress((void**)&p_kprojh, d_kprojh);

    // one-time precomputation
    k_init<<<(BB*HH + 255)/256, 256>>>(efs);
    k_embed<<<SS*BB, 128>>>(tgt, emb);
    k_enc2bf<<<LTD, 256>>>(enc);
    {   // gi_emb[s,b,:] = relu(emb) @ Wih0[:, :EE]^T + bih0
        dim3 g(SS*BB/128, (3*HH)/64, 1);
        k_sgemm<<<g, 256>>>(p_xemb, EE, 0, Wih0, EE+HH, 0, bih0, 0,
                            p_giEmb, 3*HH, 0, nullptr, SS*BB, 3*HH, EE);
    }
    {   // kproj[l,t,b,:] = enc @ Kw[l]^T + Kb[l], bf16 output only
        dim3 g(TT*BB/128, (AT+63)/64, LL);
        k_sgemm<<<g, 256>>>(enc, HH, (long long)TT*BB*HH,
                            Kw, HH, (long long)AT*HH,
                            Kb, AT,
                            nullptr, AT, (long long)TT*BB*AT,
                            p_kprojh,
                            TT*BB, AT, HH);
    }

    // sequential decode loop: 7 nodes per step (gh0/gh1 overlapped inside front node)
    for (int s = 0; s < SS; s++){
        int cur = s & 1;
        k_front<<<3392, 256>>>(Qw, Qb, Whh0, Whh1, cur);
        { dim3 gs(LTD/64, BB); k_scores<<<gs, 256>>>(Vw, Vb); }
        { dim3 gc(BB, 4); k_ctx<<<gc, 256>>>(); }
        k_gru1<<<96, 256>>>(0, cur, Wih0, Wih1);
        k_gates0<<<BB*HH/256, 256>>>(cur, s, bhh0);
        k_gru1<<<96, 256>>>(2, cur, Wih0, Wih1);
        k_gates1<<<BB*HH/256, 256>>>(cur, s, bih1, bhh1);
    }

    {   // deferred output projection on tensor cores (tf32)
        dim3 g(SS*BB/128, (VV + 63)/64, 1);
        k_proj<<<g, 256>>>(Pw, Pb, out);
    }
}